// round 1
// baseline (speedup 1.0000x reference)
#include <cuda_runtime.h>

#define NB 32
#define DIM 4096
#define NH 32
#define NKV 8
#define HD 128
#define MAXS 4096
#define POS_NEW 2047
#define NSPLIT 8
#define PPS 256          // positions per split (2048/8)
#define FQKV 6144
#define NDSPLIT 8
#define DRANGE 512       // 4096/8

typedef unsigned long long ull;

__device__ __forceinline__ ull ffma2(ull a, ull b, ull c) {
    ull d;
    asm("fma.rn.f32x2 %0, %1, %2, %3;" : "=l"(d) : "l"(a), "l"(b), "l"(c));
    return d;
}
__device__ __forceinline__ float2 u2f(ull r) {
    float2 v;
    asm("mov.b64 {%0, %1}, %2;" : "=f"(v.x), "=f"(v.y) : "l"(r));
    return v;
}
__device__ __forceinline__ ull f2u(float x, float y) {
    ull r;
    asm("mov.b64 %0, {%1, %2};" : "=l"(r) : "f"(x), "f"(y));
    return r;
}

// ---------------- scratch (device globals; no allocation) ----------------
__device__ __align__(16) float2 g_xt2[(DIM / 2) * NB];           // x transposed, pair-packed
__device__ __align__(16) float  g_part[NDSPLIT * NB * FQKV];     // gemm partials (reused for WO)
__device__ __align__(16) float  g_qkv[NB * FQKV];                // q | k_raw | v_raw
__device__ __align__(16) float  g_kr[NB * NKV * HD];             // roped new k
__device__ __align__(16) float  g_vr[NB * NKV * HD];             // roped new v
__device__ __align__(16) float  g_po[NSPLIT * NB * NH * HD];     // partial O per split
__device__ float g_pm[NSPLIT * NB * NH];
__device__ float g_pl[NSPLIT * NB * NH];
__device__ __align__(16) float2 g_at2[(DIM / 2) * NB];           // attn out transposed, pair-packed

// ---------------- kernel 1: transpose x -> xt2[d2][b] = (x[b][2d2], x[b][2d2+1]) -----
__global__ void k_transpose(const float* __restrict__ x) {
    __shared__ __align__(16) float t[256][33];
    int d0 = blockIdx.x * 256;
    int tid = threadIdx.x;
#pragma unroll 4
    for (int bb = 0; bb < NB; bb++)
        t[tid][bb] = x[bb * DIM + d0 + tid];
    __syncthreads();
#pragma unroll 4
    for (int k = 0; k < 16; k++) {
        int idx = k * 256 + tid;     // 0..4095 over (d2l, b)
        int d2l = idx >> 5;          // 0..127
        int b   = idx & 31;
        g_xt2[(d0 / 2 + d2l) * NB + b] = make_float2(t[2 * d2l][b], t[2 * d2l + 1][b]);
    }
}

// ---------------- kernel 2: skinny GEMM out[b][f] = sum_d xT[d][b] * w[f][d] ----------
// mode 0: x = g_xt2 (QKV, w0=wq f<4096, w1=wk, w2=wv); mode 1: x = g_at2 (WO, w0 only)
// grid: (F/64, NDSPLIT), block 256. Partials into g_part[dsplit][b][f].
__global__ void k_gemm(int mode, const float* __restrict__ w0, const float* __restrict__ w1,
                       const float* __restrict__ w2, int F) {
    __shared__ __align__(16) float2 xs[32][32];   // 64 d x 32 b   (8KB)
    __shared__ __align__(16) float  ws[64][64];   // 64 f x 64 d   (16KB)
    int tid = threadIdx.x, lane = tid & 31, warp = tid >> 5;
    int ftile = blockIdx.x * 64;
    int dsplit = blockIdx.y;

    const float2* xt2 = mode ? g_at2 : g_xt2;
    const float* w = w0;
    int frow = ftile;
    if (mode == 0) {
        if (ftile >= 5120)      { w = w2; frow = ftile - 5120; }
        else if (ftile >= 4096) { w = w1; frow = ftile - 4096; }
    }

    ull acc[8];
#pragma unroll
    for (int f = 0; f < 8; f++) acc[f] = 0ULL;

    for (int c = 0; c < DRANGE / 64; c++) {   // 8 chunks of 64 d
        int d0 = dsplit * DRANGE + c * 64;
        __syncthreads();
        // stage x: contiguous 8KB region of xt2
        {
            const float4* src = (const float4*)(xt2 + (size_t)(d0 / 2) * NB);
            float4* dst = (float4*)&xs[0][0];
            dst[tid]       = src[tid];
            dst[tid + 256] = src[tid + 256];
        }
        // stage w: 64 rows x 64 floats, coalesced
        {
            const float* wbase = w + (size_t)frow * DIM + d0;
#pragma unroll
            for (int i = 0; i < 4; i++) {
                int idx = i * 256 + tid;        // over 1024 float4
                int r = idx >> 4, cc = idx & 15;
                ((float4*)ws)[idx] = *(const float4*)(wbase + (size_t)r * DIM + cc * 4);
            }
        }
        __syncthreads();
#pragma unroll 4
        for (int j2 = 0; j2 < 16; j2++) {
            ull xa = *(const ull*)&xs[2 * j2][lane];
            ull xb = *(const ull*)&xs[2 * j2 + 1][lane];
#pragma unroll
            for (int f = 0; f < 8; f++) {
                ulonglong2 wv = *(const ulonglong2*)&ws[warp * 8 + f][4 * j2];
                acc[f] = ffma2(wv.x, xa, acc[f]);
                acc[f] = ffma2(wv.y, xb, acc[f]);
            }
        }
    }
#pragma unroll
    for (int f = 0; f < 8; f++) {
        float2 v = u2f(acc[f]);
        g_part[((size_t)dsplit * NB + lane) * F + ftile + warp * 8 + f] = v.x + v.y;
    }
}

// ---------------- kernel 3: reduce partials over NDSPLIT ----------------
__global__ void k_reduce(float* __restrict__ out, int N) {
    int i = blockIdx.x * 256 + threadIdx.x;
    if (i < N) {
        float s = 0.f;
#pragma unroll
        for (int k = 0; k < NDSPLIT; k++) s += g_part[(size_t)k * N + i];
        float* o = out ? out : g_qkv;
        o[i] = s;
    }
}

// ---------------- kernel 4: rope new k and v ----------------
__global__ void k_rope(const float* __restrict__ cosv, const float* __restrict__ sinv) {
    int b = blockIdx.x;
    int tid = threadIdx.x;
    for (int p = tid; p < NKV * 64; p += 256) {
        int h = p >> 6, j = p & 63;
        float c = cosv[j], s = sinv[j];
        const float* kr = &g_qkv[b * FQKV + 4096 + h * HD + 2 * j];
        const float* vr = &g_qkv[b * FQKV + 5120 + h * HD + 2 * j];
        float r = kr[0], im = kr[1];
        g_kr[(b * NKV + h) * HD + 2 * j]     = r * c - im * s;
        g_kr[(b * NKV + h) * HD + 2 * j + 1] = r * s + im * c;
        r = vr[0]; im = vr[1];
        g_vr[(b * NKV + h) * HD + 2 * j]     = r * c - im * s;
        g_vr[(b * NKV + h) * HD + 2 * j + 1] = r * s + im * c;
    }
}

// ---------------- kernel 5: flash-decode attention, split over positions --------------
// grid (NSPLIT, NKV, NB), block 256 (8 warps x 32 positions each)
__global__ void k_attn(const float* __restrict__ kc, const float* __restrict__ vc) {
    __shared__ __align__(16) float s_sc[PPS][4];        // scores -> p       (4KB)
    __shared__ __align__(16) float s_os[8][4][HD];      // per-warp O acc    (16KB)
    __shared__ float s_wm[8][4];
    __shared__ float s_wl[8][4];
    __shared__ float s_mb[4];
    int split = blockIdx.x, kvh = blockIdx.y, b = blockIdx.z;
    int tid = threadIdx.x, lane = tid & 31, warp = tid >> 5;

    ulonglong2 qq[4];
#pragma unroll
    for (int h = 0; h < 4; h++)
        qq[h] = ((const ulonglong2*)&g_qkv[b * FQKV + (kvh * 4 + h) * HD])[lane];

    const float scale = 0.08838834764831845f;  // 1/sqrt(128)
    float m0 = -1e30f, m1 = -1e30f, m2 = -1e30f, m3 = -1e30f;
    int p0 = split * PPS + warp * 32;

    // ---- pass 1: scores + per-warp max ----
#pragma unroll 2
    for (int i = 0; i < 32; i++) {
        int pos = p0 + i;
        const float* krow = (pos == POS_NEW)
            ? &g_kr[(b * NKV + kvh) * HD]
            : (kc + (((size_t)b * MAXS + pos) * NKV + kvh) * HD);
        ulonglong2 kk = ((const ulonglong2*)krow)[lane];
        float4 sc;
        {
            float2 t;
            t = u2f(ffma2(qq[0].x, kk.x, ffma2(qq[0].y, kk.y, 0ULL))); sc.x = t.x + t.y;
            t = u2f(ffma2(qq[1].x, kk.x, ffma2(qq[1].y, kk.y, 0ULL))); sc.y = t.x + t.y;
            t = u2f(ffma2(qq[2].x, kk.x, ffma2(qq[2].y, kk.y, 0ULL))); sc.z = t.x + t.y;
            t = u2f(ffma2(qq[3].x, kk.x, ffma2(qq[3].y, kk.y, 0ULL))); sc.w = t.x + t.y;
        }
#pragma unroll
        for (int off = 16; off > 0; off >>= 1) {
            sc.x += __shfl_xor_sync(0xffffffffu, sc.x, off);
            sc.y += __shfl_xor_sync(0xffffffffu, sc.y, off);
            sc.z += __shfl_xor_sync(0xffffffffu, sc.z, off);
            sc.w += __shfl_xor_sync(0xffffffffu, sc.w, off);
        }
        sc.x *= scale; sc.y *= scale; sc.z *= scale; sc.w *= scale;
        m0 = fmaxf(m0, sc.x); m1 = fmaxf(m1, sc.y);
        m2 = fmaxf(m2, sc.z); m3 = fmaxf(m3, sc.w);
        if (lane == 0) *(float4*)&s_sc[warp * 32 + i][0] = sc;
    }
    if (lane == 0) { s_wm[warp][0] = m0; s_wm[warp][1] = m1; s_wm[warp][2] = m2; s_wm[warp][3] = m3; }
    __syncthreads();

    // ---- pass 2: block max, p = exp(s - m), per-warp l sums ----
    float mb[4];
#pragma unroll
    for (int h = 0; h < 4; h++) {
        float v = s_wm[0][h];
#pragma unroll
        for (int ww = 1; ww < 8; ww++) v = fmaxf(v, s_wm[ww][h]);
        mb[h] = v;
    }
    float p[4];
#pragma unroll
    for (int h = 0; h < 4; h++) {
        p[h] = __expf(s_sc[tid][h] - mb[h]);
        s_sc[tid][h] = p[h];
    }
    float l[4] = {p[0], p[1], p[2], p[3]};
#pragma unroll
    for (int off = 16; off > 0; off >>= 1) {
        l[0] += __shfl_xor_sync(0xffffffffu, l[0], off);
        l[1] += __shfl_xor_sync(0xffffffffu, l[1], off);
        l[2] += __shfl_xor_sync(0xffffffffu, l[2], off);
        l[3] += __shfl_xor_sync(0xffffffffu, l[3], off);
    }
    if (lane == 0) { s_wl[warp][0] = l[0]; s_wl[warp][1] = l[1]; s_wl[warp][2] = l[2]; s_wl[warp][3] = l[3]; }
    if (tid < 4) s_mb[tid] = mb[tid];
    __syncthreads();

    // ---- pass 3: O += p * V ----
    ull a01[4], a23[4];
#pragma unroll
    for (int h = 0; h < 4; h++) { a01[h] = 0ULL; a23[h] = 0ULL; }
#pragma unroll 2
    for (int i = 0; i < 32; i++) {
        int pos = p0 + i;
        const float* vrow = (pos == POS_NEW)
            ? &g_vr[(b * NKV + kvh) * HD]
            : (vc + (((size_t)b * MAXS + pos) * NKV + kvh) * HD);
        ulonglong2 vv = ((const ulonglong2*)vrow)[lane];
        float4 pp = *(const float4*)&s_sc[warp * 32 + i][0];
        ull pu;
        pu = f2u(pp.x, pp.x); a01[0] = ffma2(pu, vv.x, a01[0]); a23[0] = ffma2(pu, vv.y, a23[0]);
        pu = f2u(pp.y, pp.y); a01[1] = ffma2(pu, vv.x, a01[1]); a23[1] = ffma2(pu, vv.y, a23[1]);
        pu = f2u(pp.z, pp.z); a01[2] = ffma2(pu, vv.x, a01[2]); a23[2] = ffma2(pu, vv.y, a23[2]);
        pu = f2u(pp.w, pp.w); a01[3] = ffma2(pu, vv.x, a01[3]); a23[3] = ffma2(pu, vv.y, a23[3]);
    }
#pragma unroll
    for (int h = 0; h < 4; h++) {
        float2 lo = u2f(a01[h]), hi = u2f(a23[h]);
        *(float4*)&s_os[warp][h][lane * 4] = make_float4(lo.x, lo.y, hi.x, hi.y);
    }
    __syncthreads();

    // ---- final: cross-warp sum, write partials ----
#pragma unroll
    for (int k = 0; k < 2; k++) {
        int o = tid + k * 256;
        int h = o >> 7, d = o & 127;
        float s = 0.f;
#pragma unroll
        for (int ww = 0; ww < 8; ww++) s += s_os[ww][h][d];
        g_po[(((size_t)split * NB + b) * NH + kvh * 4 + h) * HD + d] = s;
    }
    if (tid < 4) {
        float gl = 0.f;
#pragma unroll
        for (int ww = 0; ww < 8; ww++) gl += s_wl[ww][tid];
        g_pl[((size_t)split * NB + b) * NH + kvh * 4 + tid] = gl;
        g_pm[((size_t)split * NB + b) * NH + kvh * 4 + tid] = s_mb[tid];
    }
}

// ---------------- kernel 6: combine splits, write attn transposed for WO --------------
// grid (NH, NB), block 64
__global__ void k_combine() {
    int gh = blockIdx.x, b = blockIdx.y;
    int t = threadIdx.x;
    __shared__ float s_w[NSPLIT];
    __shared__ float s_gl;
    if (t == 0) {
        float ms[NSPLIT];
        float gm = -1e30f;
#pragma unroll
        for (int s = 0; s < NSPLIT; s++) {
            ms[s] = g_pm[((size_t)s * NB + b) * NH + gh];
            gm = fmaxf(gm, ms[s]);
        }
        float gl = 0.f;
#pragma unroll
        for (int s = 0; s < NSPLIT; s++) {
            float wv = __expf(ms[s] - gm);
            s_w[s] = wv;
            gl += wv * g_pl[((size_t)s * NB + b) * NH + gh];
        }
        s_gl = gl;
    }
    __syncthreads();
    float inv = 1.0f / s_gl;
    float o0 = 0.f, o1 = 0.f;
#pragma unroll
    for (int s = 0; s < NSPLIT; s++) {
        const float* po = &g_po[(((size_t)s * NB + b) * NH + gh) * HD];
        float wv = s_w[s];
        o0 += wv * po[2 * t];
        o1 += wv * po[2 * t + 1];
    }
    g_at2[(size_t)(gh * 64 + t) * NB + b] = make_float2(o0 * inv, o1 * inv);
}

// ---------------- launcher ----------------
extern "C" void kernel_launch(void* const* d_in, const int* in_sizes, int n_in,
                              void* d_out, int out_size) {
    const float* x  = (const float*)d_in[0];
    const float* tc = (const float*)d_in[2];
    const float* ts = (const float*)d_in[3];
    const float* wq = (const float*)d_in[4];
    const float* wk = (const float*)d_in[5];
    const float* wv = (const float*)d_in[6];
    const float* wo = (const float*)d_in[7];
    const float* kc = (const float*)d_in[8];
    const float* vc = (const float*)d_in[9];
    float* out = (float*)d_out;

    k_transpose<<<16, 256>>>(x);
    k_gemm<<<dim3(FQKV / 64, NDSPLIT), 256>>>(0, wq, wk, wv, FQKV);
    k_reduce<<<(NB * FQKV + 255) / 256, 256>>>(nullptr, NB * FQKV);
    k_rope<<<NB, 256>>>(tc, ts);
    k_attn<<<dim3(NSPLIT, NKV, NB), 256>>>(kc, vc);
    k_combine<<<dim3(NH, NB), 64>>>();
    k_gemm<<<dim3(DIM / 64, NDSPLIT), 256>>>(1, wo, nullptr, nullptr, DIM);
    k_reduce<<<(NB * DIM + 255) / 256, 256>>>(out, NB * DIM);
}

// round 2
// speedup vs baseline: 1.1618x; 1.1618x over previous
#include <cuda_runtime.h>

#define NB 32
#define DIM 4096
#define NH 32
#define NKV 8
#define HD 128
#define MAXS 4096
#define POS_NEW 2047
#define NSPLIT 8
#define PPS 256          // positions per split (2048/8)
#define FQKV 6144
#define NDSPLIT 8
#define DRANGE 512       // 4096/8

typedef unsigned long long ull;

__device__ __forceinline__ ull ffma2(ull a, ull b, ull c) {
    ull d;
    asm("fma.rn.f32x2 %0, %1, %2, %3;" : "=l"(d) : "l"(a), "l"(b), "l"(c));
    return d;
}
__device__ __forceinline__ float2 u2f(ull r) {
    float2 v;
    asm("mov.b64 {%0, %1}, %2;" : "=f"(v.x), "=f"(v.y) : "l"(r));
    return v;
}
__device__ __forceinline__ ull f2u(float x, float y) {
    ull r;
    asm("mov.b64 %0, {%1, %2};" : "=l"(r) : "f"(x), "f"(y));
    return r;
}

// ---------------- scratch (device globals; no allocation) ----------------
__device__ __align__(16) float2 g_xt2[(DIM / 2) * NB];           // x transposed, pair-packed
__device__ __align__(16) float  g_part[NDSPLIT * NB * FQKV];     // gemm partials (reused for WO)
__device__ __align__(16) float  g_qkv[NB * FQKV];                // q (first 4096 per b used)
__device__ __align__(16) float  g_kr[NB * NKV * HD];             // roped new k
__device__ __align__(16) float  g_vr[NB * NKV * HD];             // roped new v
__device__ __align__(16) float  g_po[NSPLIT * NB * NH * HD];     // partial O per split
__device__ float g_pm[NSPLIT * NB * NH];
__device__ float g_pl[NSPLIT * NB * NH];
__device__ __align__(16) float2 g_at2[(DIM / 2) * NB];           // attn out transposed, pair-packed

// ---------------- kernel 1: transpose x -> xt2[d2][b] ----------------
__global__ void k_transpose(const float* __restrict__ x) {
    __shared__ __align__(16) float t[256][33];
    int d0 = blockIdx.x * 256;
    int tid = threadIdx.x;
#pragma unroll 4
    for (int bb = 0; bb < NB; bb++)
        t[tid][bb] = x[bb * DIM + d0 + tid];
    __syncthreads();
#pragma unroll 4
    for (int k = 0; k < 16; k++) {
        int idx = k * 256 + tid;
        int d2l = idx >> 5;
        int b   = idx & 31;
        g_xt2[(d0 / 2 + d2l) * NB + b] = make_float2(t[2 * d2l][b], t[2 * d2l + 1][b]);
    }
}

// ---------------- kernel 2: skinny GEMM out[b][f] = sum_d xT[d][b] * w[f][d] ----------
__global__ void k_gemm(int mode, const float* __restrict__ w0, const float* __restrict__ w1,
                       const float* __restrict__ w2, int F) {
    __shared__ __align__(16) float2 xs[32][32];   // 64 d x 32 b
    __shared__ __align__(16) float  ws[64][64];   // 64 f x 64 d
    int tid = threadIdx.x, lane = tid & 31, warp = tid >> 5;
    int ftile = blockIdx.x * 64;
    int dsplit = blockIdx.y;

    const float2* xt2 = mode ? g_at2 : g_xt2;
    const float* w = w0;
    int frow = ftile;
    if (mode == 0) {
        if (ftile >= 5120)      { w = w2; frow = ftile - 5120; }
        else if (ftile >= 4096) { w = w1; frow = ftile - 4096; }
    }

    ull acc[8];
#pragma unroll
    for (int f = 0; f < 8; f++) acc[f] = 0ULL;

    for (int c = 0; c < DRANGE / 64; c++) {
        int d0 = dsplit * DRANGE + c * 64;
        __syncthreads();
        {
            const float4* src = (const float4*)(xt2 + (size_t)(d0 / 2) * NB);
            float4* dst = (float4*)&xs[0][0];
            dst[tid]       = src[tid];
            dst[tid + 256] = src[tid + 256];
        }
        {
            const float* wbase = w + (size_t)frow * DIM + d0;
#pragma unroll
            for (int i = 0; i < 4; i++) {
                int idx = i * 256 + tid;
                int r = idx >> 4, cc = idx & 15;
                ((float4*)ws)[idx] = *(const float4*)(wbase + (size_t)r * DIM + cc * 4);
            }
        }
        __syncthreads();
#pragma unroll 4
        for (int j2 = 0; j2 < 16; j2++) {
            ull xa = *(const ull*)&xs[2 * j2][lane];
            ull xb = *(const ull*)&xs[2 * j2 + 1][lane];
#pragma unroll
            for (int f = 0; f < 8; f++) {
                ulonglong2 wv = *(const ulonglong2*)&ws[warp * 8 + f][4 * j2];
                acc[f] = ffma2(wv.x, xa, acc[f]);
                acc[f] = ffma2(wv.y, xb, acc[f]);
            }
        }
    }
#pragma unroll
    for (int f = 0; f < 8; f++) {
        float2 v = u2f(acc[f]);
        g_part[((size_t)dsplit * NB + lane) * F + ftile + warp * 8 + f] = v.x + v.y;
    }
}

// ---------------- kernel 3: reduce QKV partials + fused rope ----------------
// thread handles one float2 (adjacent pair) -> rope pairs stay within thread
__global__ void k_reduce_rope(const float* __restrict__ cosv, const float* __restrict__ sinv) {
    int i2 = blockIdx.x * 256 + threadIdx.x;        // over NB*FQKV/2 = 98304
    float2 s = make_float2(0.f, 0.f);
#pragma unroll
    for (int k = 0; k < NDSPLIT; k++) {
        float2 v = ((const float2*)g_part)[(size_t)k * (NB * FQKV / 2) + i2];
        s.x += v.x; s.y += v.y;
    }
    int b = i2 / (FQKV / 2), f2 = i2 % (FQKV / 2);
    int f = f2 * 2;
    if (f < 4096) {
        ((float2*)g_qkv)[i2] = s;                    // q region (layout matches)
    } else {
        int rel = f - 4096;                          // 0..2047
        int isv = rel >= 1024;
        int rr  = rel & 1023;                        // within NKV*HD
        int j   = (rr & 127) >> 1;
        float c = cosv[j], sn = sinv[j];
        float ro = s.x * c - s.y * sn;
        float io = s.x * sn + s.y * c;
        float* dst = isv ? g_vr : g_kr;
        ((float2*)dst)[(size_t)b * (NKV * HD / 2) + (rr >> 1)] = make_float2(ro, io);
    }
}

// ---------------- kernel 3b: generic float2 reduce for WO output ----------------
__global__ void k_reduce_out(float* __restrict__ out) {
    int i2 = blockIdx.x * 256 + threadIdx.x;        // over NB*DIM/2 = 65536
    float2 s = make_float2(0.f, 0.f);
#pragma unroll
    for (int k = 0; k < NDSPLIT; k++) {
        float2 v = ((const float2*)g_part)[(size_t)k * (NB * DIM / 2) + i2];
        s.x += v.x; s.y += v.y;
    }
    ((float2*)out)[i2] = s;
}

// ---------------- kernel 4: flash-decode attention (lane-owns-position) -------------
// grid (NSPLIT, NKV, NB), block 256 (8 warps x 32 positions each)
#define KROW 36   // padded row stride in floats (144B, 16B aligned)
__global__ void __launch_bounds__(256, 3) k_attn(const float* __restrict__ kc,
                                                 const float* __restrict__ vc) {
    __shared__ __align__(16) float  s_k[8][32 * KROW];   // per-warp K tile (36.9KB)
    __shared__ __align__(16) float4 s_q[4][32];          // q packed per head (2KB)
    __shared__ __align__(16) float4 s_p[256];            // softmax probs (4KB)
    __shared__ __align__(16) float  s_os[8][4][HD];      // per-warp O acc (16KB)
    __shared__ float s_wm[8][4], s_wl[8][4], s_mb[4];

    int split = blockIdx.x, kvh = blockIdx.y, b = blockIdx.z;
    int tid = threadIdx.x, lane = tid & 31, warp = tid >> 5;
    int p0 = split * PPS + warp * 32;

    // stage q: 4 heads x 128 floats = 128 float4
    if (tid < 128) {
        int h = tid >> 5, j4 = tid & 31;
        s_q[h][j4] = ((const float4*)&g_qkv[b * FQKV + (kvh * 4 + h) * HD])[j4];
    }
    __syncthreads();

    // ---- pass 1: scores; each lane owns position p0+lane ----
    float* kbuf = s_k[warp];
    int r_ = lane >> 3, jj = lane & 7;
    const float* knew = &g_kr[(b * NKV + kvh) * HD];

    float4 pre[8];
#pragma unroll
    for (int i = 0; i < 8; i++) {
        int r = i * 4 + r_;
        int pos = p0 + r;
        const float* src = (pos == POS_NEW) ? knew
                         : kc + (((size_t)b * MAXS + pos) * NKV + kvh) * HD;
        pre[i] = *(const float4*)(src + jj * 4);
    }

    ull acc[4];
#pragma unroll
    for (int h = 0; h < 4; h++) acc[h] = 0ULL;

#pragma unroll
    for (int c = 0; c < 4; c++) {
#pragma unroll
        for (int i = 0; i < 8; i++) {
            int r = i * 4 + r_;
            *(float4*)&kbuf[r * KROW + jj * 4] = pre[i];
        }
        if (c < 3) {
#pragma unroll
            for (int i = 0; i < 8; i++) {
                int r = i * 4 + r_;
                int pos = p0 + r;
                const float* src = (pos == POS_NEW) ? knew
                                 : kc + (((size_t)b * MAXS + pos) * NKV + kvh) * HD;
                pre[i] = *(const float4*)(src + (c + 1) * 32 + jj * 4);
            }
        }
        __syncwarp();
#pragma unroll
        for (int j4 = 0; j4 < 8; j4++) {
            ulonglong2 k2 = *(const ulonglong2*)&kbuf[lane * KROW + j4 * 4];
#pragma unroll
            for (int h = 0; h < 4; h++) {
                ulonglong2 q2 = *(const ulonglong2*)&s_q[h][c * 8 + j4];
                acc[h] = ffma2(q2.x, k2.x, acc[h]);
                acc[h] = ffma2(q2.y, k2.y, acc[h]);
            }
        }
        __syncwarp();
    }

    const float scale = 0.08838834764831845f;  // 1/sqrt(128)
    float sc[4], m[4];
#pragma unroll
    for (int h = 0; h < 4; h++) {
        float2 t = u2f(acc[h]);
        sc[h] = (t.x + t.y) * scale;
        m[h] = sc[h];
    }
#pragma unroll
    for (int off = 16; off > 0; off >>= 1) {
#pragma unroll
        for (int h = 0; h < 4; h++)
            m[h] = fmaxf(m[h], __shfl_xor_sync(0xffffffffu, m[h], off));
    }
    if (lane == 0) {
#pragma unroll
        for (int h = 0; h < 4; h++) s_wm[warp][h] = m[h];
    }
    __syncthreads();

    // block max, p = exp(s - m), per-warp l sums
    float mb[4];
#pragma unroll
    for (int h = 0; h < 4; h++) {
        float v = s_wm[0][h];
#pragma unroll
        for (int ww = 1; ww < 8; ww++) v = fmaxf(v, s_wm[ww][h]);
        mb[h] = v;
    }
    float p[4], l[4];
#pragma unroll
    for (int h = 0; h < 4; h++) {
        p[h] = __expf(sc[h] - mb[h]);
        l[h] = p[h];
    }
    s_p[tid] = make_float4(p[0], p[1], p[2], p[3]);
#pragma unroll
    for (int off = 16; off > 0; off >>= 1) {
#pragma unroll
        for (int h = 0; h < 4; h++)
            l[h] += __shfl_xor_sync(0xffffffffu, l[h], off);
    }
    if (lane == 0) {
#pragma unroll
        for (int h = 0; h < 4; h++) s_wl[warp][h] = l[h];
    }
    if (tid < 4) s_mb[tid] = mb[tid];
    __syncthreads();

    // ---- pass 3: O += p * V  (coalesced row loads, p broadcast) ----
    const float* vnew = &g_vr[(b * NKV + kvh) * HD];
    ull a01[4], a23[4];
#pragma unroll
    for (int h = 0; h < 4; h++) { a01[h] = 0ULL; a23[h] = 0ULL; }
#pragma unroll 4
    for (int i = 0; i < 32; i++) {
        int pos = p0 + i;
        const float* vrow = (pos == POS_NEW) ? vnew
                          : vc + (((size_t)b * MAXS + pos) * NKV + kvh) * HD;
        ulonglong2 vv = ((const ulonglong2*)vrow)[lane];
        float4 pp = s_p[warp * 32 + i];
        ull pu;
        pu = f2u(pp.x, pp.x); a01[0] = ffma2(pu, vv.x, a01[0]); a23[0] = ffma2(pu, vv.y, a23[0]);
        pu = f2u(pp.y, pp.y); a01[1] = ffma2(pu, vv.x, a01[1]); a23[1] = ffma2(pu, vv.y, a23[1]);
        pu = f2u(pp.z, pp.z); a01[2] = ffma2(pu, vv.x, a01[2]); a23[2] = ffma2(pu, vv.y, a23[2]);
        pu = f2u(pp.w, pp.w); a01[3] = ffma2(pu, vv.x, a01[3]); a23[3] = ffma2(pu, vv.y, a23[3]);
    }
#pragma unroll
    for (int h = 0; h < 4; h++) {
        float2 lo = u2f(a01[h]), hi = u2f(a23[h]);
        *(float4*)&s_os[warp][h][lane * 4] = make_float4(lo.x, lo.y, hi.x, hi.y);
    }
    __syncthreads();

    // ---- final: cross-warp sum, write partials ----
#pragma unroll
    for (int k = 0; k < 2; k++) {
        int o = tid + k * 256;
        int h = o >> 7, d = o & 127;
        float s = 0.f;
#pragma unroll
        for (int ww = 0; ww < 8; ww++) s += s_os[ww][h][d];
        g_po[(((size_t)split * NB + b) * NH + kvh * 4 + h) * HD + d] = s;
    }
    if (tid < 4) {
        float gl = 0.f;
#pragma unroll
        for (int ww = 0; ww < 8; ww++) gl += s_wl[ww][tid];
        g_pl[((size_t)split * NB + b) * NH + kvh * 4 + tid] = gl;
        g_pm[((size_t)split * NB + b) * NH + kvh * 4 + tid] = s_mb[tid];
    }
}

// ---------------- kernel 6: combine splits, write attn transposed for WO --------------
__global__ void k_combine() {
    int gh = blockIdx.x, b = blockIdx.y;
    int t = threadIdx.x;
    __shared__ float s_w[NSPLIT];
    __shared__ float s_gl;
    if (t == 0) {
        float ms[NSPLIT];
        float gm = -1e30f;
#pragma unroll
        for (int s = 0; s < NSPLIT; s++) {
            ms[s] = g_pm[((size_t)s * NB + b) * NH + gh];
            gm = fmaxf(gm, ms[s]);
        }
        float gl = 0.f;
#pragma unroll
        for (int s = 0; s < NSPLIT; s++) {
            float wv = __expf(ms[s] - gm);
            s_w[s] = wv;
            gl += wv * g_pl[((size_t)s * NB + b) * NH + gh];
        }
        s_gl = gl;
    }
    __syncthreads();
    float inv = 1.0f / s_gl;
    float o0 = 0.f, o1 = 0.f;
#pragma unroll
    for (int s = 0; s < NSPLIT; s++) {
        const float* po = &g_po[(((size_t)s * NB + b) * NH + gh) * HD];
        float wv = s_w[s];
        o0 += wv * po[2 * t];
        o1 += wv * po[2 * t + 1];
    }
    g_at2[(size_t)(gh * 64 + t) * NB + b] = make_float2(o0 * inv, o1 * inv);
}

// ---------------- launcher ----------------
extern "C" void kernel_launch(void* const* d_in, const int* in_sizes, int n_in,
                              void* d_out, int out_size) {
    const float* x  = (const float*)d_in[0];
    const float* tc = (const float*)d_in[2];
    const float* ts = (const float*)d_in[3];
    const float* wq = (const float*)d_in[4];
    const float* wk = (const float*)d_in[5];
    const float* wv = (const float*)d_in[6];
    const float* wo = (const float*)d_in[7];
    const float* kc = (const float*)d_in[8];
    const float* vc = (const float*)d_in[9];
    float* out = (float*)d_out;

    k_transpose<<<16, 256>>>(x);
    k_gemm<<<dim3(FQKV / 64, NDSPLIT), 256>>>(0, wq, wk, wv, FQKV);
    k_reduce_rope<<<NB * FQKV / 2 / 256, 256>>>(tc, ts);
    k_attn<<<dim3(NSPLIT, NKV, NB), 256>>>(kc, vc);
    k_combine<<<dim3(NH, NB), 64>>>();
    k_gemm<<<dim3(DIM / 64, NDSPLIT), 256>>>(1, wo, nullptr, nullptr, DIM);
    k_reduce_out<<<NB * DIM / 2 / 256, 256>>>(out);
}

// round 3
// speedup vs baseline: 1.1637x; 1.0016x over previous
#include <cuda_runtime.h>

#define NB 32
#define DIM 4096
#define NH 32
#define NKV 8
#define HD 128
#define MAXS 4096
#define POS_NEW 2047
#define NSPLIT 8
#define PPS 256          // positions per split (2048/8)
#define FQKV 6144
#define NDSPLIT 8
#define DRANGE 512       // 4096/8

typedef unsigned long long ull;

__device__ __forceinline__ ull ffma2(ull a, ull b, ull c) {
    ull d;
    asm("fma.rn.f32x2 %0, %1, %2, %3;" : "=l"(d) : "l"(a), "l"(b), "l"(c));
    return d;
}
__device__ __forceinline__ float2 u2f(ull r) {
    float2 v;
    asm("mov.b64 {%0, %1}, %2;" : "=f"(v.x), "=f"(v.y) : "l"(r));
    return v;
}
__device__ __forceinline__ ull f2u(float x, float y) {
    ull r;
    asm("mov.b64 %0, {%1, %2};" : "=l"(r) : "f"(x), "f"(y));
    return r;
}

// ---------------- scratch (device globals; no allocation) ----------------
__device__ __align__(16) float2 g_xt2[(DIM / 2) * NB];
__device__ __align__(16) float  g_part[NDSPLIT * NB * FQKV];
__device__ __align__(16) float  g_qkv[NB * FQKV];
__device__ __align__(16) float  g_kr[NB * NKV * HD];
__device__ __align__(16) float  g_vr[NB * NKV * HD];
__device__ __align__(16) float  g_po[NSPLIT * NB * NH * HD];
__device__ float g_pm[NSPLIT * NB * NH];
__device__ float g_pl[NSPLIT * NB * NH];
__device__ __align__(16) float2 g_at2[(DIM / 2) * NB];

// ---------------- kernel 1: transpose x -> xt2[d2][b] ----------------
__global__ void k_transpose(const float* __restrict__ x) {
    __shared__ __align__(16) float t[256][33];
    int d0 = blockIdx.x * 256;
    int tid = threadIdx.x;
#pragma unroll
    for (int bb = 0; bb < NB; bb++)
        t[tid][bb] = x[bb * DIM + d0 + tid];
    __syncthreads();
#pragma unroll
    for (int k = 0; k < 16; k++) {
        int idx = k * 256 + tid;
        int d2l = idx >> 5;
        int b   = idx & 31;
        g_xt2[(d0 / 2 + d2l) * NB + b] = make_float2(t[2 * d2l][b], t[2 * d2l + 1][b]);
    }
}

// ---------------- kernel 2: skinny GEMM, register double-buffered ----------------
// out[b][f] = sum_d xT[d][b] * w[f][d]; partials per d-split into g_part.
__global__ void __launch_bounds__(256, 4)
k_gemm(int mode, const float* __restrict__ w0, const float* __restrict__ w1,
       const float* __restrict__ w2, int F) {
    __shared__ __align__(16) float2 xs[32][32];   // 64 d x 32 b
    __shared__ __align__(16) float  ws[64][64];   // 64 f x 64 d
    int tid = threadIdx.x, lane = tid & 31, warp = tid >> 5;
    int ftile = blockIdx.x * 64;
    int dsplit = blockIdx.y;

    const float2* xt2 = mode ? g_at2 : g_xt2;
    const float* w = w0;
    int frow = ftile;
    if (mode == 0) {
        if (ftile >= 5120)      { w = w2; frow = ftile - 5120; }
        else if (ftile >= 4096) { w = w1; frow = ftile - 4096; }
    }

    const float4* xbase = (const float4*)(xt2 + (size_t)(dsplit * DRANGE / 2) * NB);
    const float* wt = w + (size_t)frow * DIM + dsplit * DRANGE
                        + (size_t)(tid >> 4) * DIM + (tid & 15) * 4;

    // prefetch chunk 0
    float4 px0 = xbase[tid];
    float4 px1 = xbase[tid + 256];
    float4 pw0 = *(const float4*)(wt);
    float4 pw1 = *(const float4*)(wt + 16 * DIM);
    float4 pw2 = *(const float4*)(wt + 32 * DIM);
    float4 pw3 = *(const float4*)(wt + 48 * DIM);

    ull acc[8];
#pragma unroll
    for (int f = 0; f < 8; f++) acc[f] = 0ULL;

    for (int c = 0; c < 8; c++) {
        __syncthreads();
        ((float4*)&xs[0][0])[tid]       = px0;
        ((float4*)&xs[0][0])[tid + 256] = px1;
        {
            float4* wsd = (float4*)ws;
            wsd[tid]       = pw0;
            wsd[tid + 256] = pw1;
            wsd[tid + 512] = pw2;
            wsd[tid + 768] = pw3;
        }
        if (c < 7) {
            const float4* xn = xbase + (c + 1) * 512;
            px0 = xn[tid];
            px1 = xn[tid + 256];
            const float* wn = wt + (c + 1) * 64;
            pw0 = *(const float4*)(wn);
            pw1 = *(const float4*)(wn + 16 * DIM);
            pw2 = *(const float4*)(wn + 32 * DIM);
            pw3 = *(const float4*)(wn + 48 * DIM);
        }
        __syncthreads();
#pragma unroll 4
        for (int j2 = 0; j2 < 16; j2++) {
            ull xa = *(const ull*)&xs[2 * j2][lane];
            ull xb = *(const ull*)&xs[2 * j2 + 1][lane];
#pragma unroll
            for (int f = 0; f < 8; f++) {
                ulonglong2 wv = *(const ulonglong2*)&ws[warp * 8 + f][4 * j2];
                acc[f] = ffma2(wv.x, xa, acc[f]);
                acc[f] = ffma2(wv.y, xb, acc[f]);
            }
        }
    }
#pragma unroll
    for (int f = 0; f < 8; f++) {
        float2 v = u2f(acc[f]);
        g_part[((size_t)dsplit * NB + lane) * F + ftile + warp * 8 + f] = v.x + v.y;
    }
}

// ---------------- kernel 3: reduce QKV partials + fused rope ----------------
__global__ void k_reduce_rope(const float* __restrict__ cosv, const float* __restrict__ sinv) {
    int i2 = blockIdx.x * 256 + threadIdx.x;        // over NB*FQKV/2
    float2 s = make_float2(0.f, 0.f);
#pragma unroll
    for (int k = 0; k < NDSPLIT; k++) {
        float2 v = ((const float2*)g_part)[(size_t)k * (NB * FQKV / 2) + i2];
        s.x += v.x; s.y += v.y;
    }
    int b = i2 / (FQKV / 2), f2 = i2 % (FQKV / 2);
    int f = f2 * 2;
    if (f < 4096) {
        ((float2*)g_qkv)[i2] = s;
    } else {
        int rel = f - 4096;
        int isv = rel >= 1024;
        int rr  = rel & 1023;
        int j   = (rr & 127) >> 1;
        float c = cosv[j], sn = sinv[j];
        float ro = s.x * c - s.y * sn;
        float io = s.x * sn + s.y * c;
        float* dst = isv ? g_vr : g_kr;
        ((float2*)dst)[(size_t)b * (NKV * HD / 2) + (rr >> 1)] = make_float2(ro, io);
    }
}

// ---------------- kernel 3b: float2 reduce for WO output ----------------
__global__ void k_reduce_out(float* __restrict__ out) {
    int i2 = blockIdx.x * 256 + threadIdx.x;        // over NB*DIM/2
    float2 s = make_float2(0.f, 0.f);
#pragma unroll
    for (int k = 0; k < NDSPLIT; k++) {
        float2 v = ((const float2*)g_part)[(size_t)k * (NB * DIM / 2) + i2];
        s.x += v.x; s.y += v.y;
    }
    ((float2*)out)[i2] = s;
}

// ---------------- kernel 4: flash-decode attention ----------------
// grid (NSPLIT, NKV, NB), block 256 (8 warps x 32 positions each)
#define KROW 36   // padded row stride in floats (conflict-free, 16B aligned)
__global__ void __launch_bounds__(256, 4) k_attn(const float* __restrict__ kc,
                                                 const float* __restrict__ vc) {
    // s_ko: per-warp K tile (pass 1), reused as per-warp O accumulator (pass 3)
    __shared__ __align__(16) float  s_ko[8][32 * KROW];  // 36.9KB
    __shared__ __align__(16) float4 s_q[4][32];          // 2KB
    __shared__ __align__(16) float4 s_p[256];            // 4KB
    __shared__ float s_wm[8][4], s_wl[8][4], s_mb[4];

    int split = blockIdx.x, kvh = blockIdx.y, b = blockIdx.z;
    int tid = threadIdx.x, lane = tid & 31, warp = tid >> 5;
    int p0 = split * PPS + warp * 32;

    if (tid < 128) {
        int h = tid >> 5, j4 = tid & 31;
        s_q[h][j4] = ((const float4*)&g_qkv[b * FQKV + (kvh * 4 + h) * HD])[j4];
    }
    __syncthreads();

    // ---- pass 1: scores; each lane owns position p0+lane ----
    float* kbuf = s_ko[warp];
    int r_ = lane >> 3, jj = lane & 7;
    const float* knew = &g_kr[(b * NKV + kvh) * HD];

    float4 pre[8];
#pragma unroll
    for (int i = 0; i < 8; i++) {
        int r = i * 4 + r_;
        int pos = p0 + r;
        const float* src = (pos == POS_NEW) ? knew
                         : kc + (((size_t)b * MAXS + pos) * NKV + kvh) * HD;
        pre[i] = *(const float4*)(src + jj * 4);
    }

    ull acc[4];
#pragma unroll
    for (int h = 0; h < 4; h++) acc[h] = 0ULL;

#pragma unroll
    for (int c = 0; c < 4; c++) {
#pragma unroll
        for (int i = 0; i < 8; i++) {
            int r = i * 4 + r_;
            *(float4*)&kbuf[r * KROW + jj * 4] = pre[i];
        }
        if (c < 3) {
#pragma unroll
            for (int i = 0; i < 8; i++) {
                int r = i * 4 + r_;
                int pos = p0 + r;
                const float* src = (pos == POS_NEW) ? knew
                                 : kc + (((size_t)b * MAXS + pos) * NKV + kvh) * HD;
                pre[i] = *(const float4*)(src + (c + 1) * 32 + jj * 4);
            }
        }
        __syncwarp();
#pragma unroll
        for (int j4 = 0; j4 < 8; j4++) {
            ulonglong2 k2 = *(const ulonglong2*)&kbuf[lane * KROW + j4 * 4];
#pragma unroll
            for (int h = 0; h < 4; h++) {
                ulonglong2 q2 = *(const ulonglong2*)&s_q[h][c * 8 + j4];
                acc[h] = ffma2(q2.x, k2.x, acc[h]);
                acc[h] = ffma2(q2.y, k2.y, acc[h]);
            }
        }
        __syncwarp();
    }

    const float scale = 0.08838834764831845f;  // 1/sqrt(128)
    float sc[4], m[4];
#pragma unroll
    for (int h = 0; h < 4; h++) {
        float2 t = u2f(acc[h]);
        sc[h] = (t.x + t.y) * scale;
        m[h] = sc[h];
    }
#pragma unroll
    for (int off = 16; off > 0; off >>= 1) {
#pragma unroll
        for (int h = 0; h < 4; h++)
            m[h] = fmaxf(m[h], __shfl_xor_sync(0xffffffffu, m[h], off));
    }
    if (lane == 0) {
#pragma unroll
        for (int h = 0; h < 4; h++) s_wm[warp][h] = m[h];
    }
    __syncthreads();

    float mb[4];
#pragma unroll
    for (int h = 0; h < 4; h++) {
        float v = s_wm[0][h];
#pragma unroll
        for (int ww = 1; ww < 8; ww++) v = fmaxf(v, s_wm[ww][h]);
        mb[h] = v;
    }
    float p[4], l[4];
#pragma unroll
    for (int h = 0; h < 4; h++) {
        p[h] = __expf(sc[h] - mb[h]);
        l[h] = p[h];
    }
    s_p[tid] = make_float4(p[0], p[1], p[2], p[3]);
#pragma unroll
    for (int off = 16; off > 0; off >>= 1) {
#pragma unroll
        for (int h = 0; h < 4; h++)
            l[h] += __shfl_xor_sync(0xffffffffu, l[h], off);
    }
    if (lane == 0) {
#pragma unroll
        for (int h = 0; h < 4; h++) s_wl[warp][h] = l[h];
    }
    if (tid < 4) s_mb[tid] = mb[tid];
    __syncthreads();

    // ---- pass 3: O += p * V (coalesced row loads, p broadcast) ----
    const float* vnew = &g_vr[(b * NKV + kvh) * HD];
    ull a01[4], a23[4];
#pragma unroll
    for (int h = 0; h < 4; h++) { a01[h] = 0ULL; a23[h] = 0ULL; }
#pragma unroll 4
    for (int i = 0; i < 32; i++) {
        int pos = p0 + i;
        const float* vrow = (pos == POS_NEW) ? vnew
                          : vc + (((size_t)b * MAXS + pos) * NKV + kvh) * HD;
        ulonglong2 vv = ((const ulonglong2*)vrow)[lane];
        float4 pp = s_p[warp * 32 + i];
        ull pu;
        pu = f2u(pp.x, pp.x); a01[0] = ffma2(pu, vv.x, a01[0]); a23[0] = ffma2(pu, vv.y, a23[0]);
        pu = f2u(pp.y, pp.y); a01[1] = ffma2(pu, vv.x, a01[1]); a23[1] = ffma2(pu, vv.y, a23[1]);
        pu = f2u(pp.z, pp.z); a01[2] = ffma2(pu, vv.x, a01[2]); a23[2] = ffma2(pu, vv.y, a23[2]);
        pu = f2u(pp.w, pp.w); a01[3] = ffma2(pu, vv.x, a01[3]); a23[3] = ffma2(pu, vv.y, a23[3]);
    }
    // O accumulator overlays the (now dead) K tile region
    float* os = &s_ko[0][0];
#pragma unroll
    for (int h = 0; h < 4; h++) {
        float2 lo = u2f(a01[h]), hi = u2f(a23[h]);
        *(float4*)&os[(warp * 4 + h) * HD + lane * 4] = make_float4(lo.x, lo.y, hi.x, hi.y);
    }
    __syncthreads();

    // ---- final: cross-warp sum, write partials ----
#pragma unroll
    for (int k = 0; k < 2; k++) {
        int o = tid + k * 256;
        int h = o >> 7, d = o & 127;
        float s = 0.f;
#pragma unroll
        for (int ww = 0; ww < 8; ww++) s += os[(ww * 4 + h) * HD + d];
        g_po[(((size_t)split * NB + b) * NH + kvh * 4 + h) * HD + d] = s;
    }
    if (tid < 4) {
        float gl = 0.f;
#pragma unroll
        for (int ww = 0; ww < 8; ww++) gl += s_wl[ww][tid];
        g_pl[((size_t)split * NB + b) * NH + kvh * 4 + tid] = gl;
        g_pm[((size_t)split * NB + b) * NH + kvh * 4 + tid] = s_mb[tid];
    }
}

// ---------------- kernel 6: combine splits, write attn transposed ----------------
__global__ void k_combine() {
    int gh = blockIdx.x, b = blockIdx.y;
    int t = threadIdx.x;
    __shared__ float s_w[NSPLIT];
    __shared__ float s_gl;
    if (t == 0) {
        float ms[NSPLIT];
        float gm = -1e30f;
#pragma unroll
        for (int s = 0; s < NSPLIT; s++) {
            ms[s] = g_pm[((size_t)s * NB + b) * NH + gh];
            gm = fmaxf(gm, ms[s]);
        }
        float gl = 0.f;
#pragma unroll
        for (int s = 0; s < NSPLIT; s++) {
            float wv = __expf(ms[s] - gm);
            s_w[s] = wv;
            gl += wv * g_pl[((size_t)s * NB + b) * NH + gh];
        }
        s_gl = gl;
    }
    __syncthreads();
    float inv = 1.0f / s_gl;
    float o0 = 0.f, o1 = 0.f;
#pragma unroll
    for (int s = 0; s < NSPLIT; s++) {
        const float* po = &g_po[(((size_t)s * NB + b) * NH + gh) * HD];
        float wv = s_w[s];
        o0 += wv * po[2 * t];
        o1 += wv * po[2 * t + 1];
    }
    g_at2[(size_t)(gh * 64 + t) * NB + b] = make_float2(o0 * inv, o1 * inv);
}

// ---------------- launcher ----------------
extern "C" void kernel_launch(void* const* d_in, const int* in_sizes, int n_in,
                              void* d_out, int out_size) {
    const float* x  = (const float*)d_in[0];
    const float* tc = (const float*)d_in[2];
    const float* ts = (const float*)d_in[3];
    const float* wq = (const float*)d_in[4];
    const float* wk = (const float*)d_in[5];
    const float* wv = (const float*)d_in[6];
    const float* wo = (const float*)d_in[7];
    const float* kc = (const float*)d_in[8];
    const float* vc = (const float*)d_in[9];
    float* out = (float*)d_out;

    k_transpose<<<16, 256>>>(x);
    k_gemm<<<dim3(FQKV / 64, NDSPLIT), 256>>>(0, wq, wk, wv, FQKV);
    k_reduce_rope<<<NB * FQKV / 2 / 256, 256>>>(tc, ts);
    k_attn<<<dim3(NSPLIT, NKV, NB), 256>>>(kc, vc);
    k_combine<<<dim3(NH, NB), 64>>>();
    k_gemm<<<dim3(DIM / 64, NDSPLIT), 256>>>(1, wo, nullptr, nullptr, DIM);
    k_reduce_out<<<NB * DIM / 2 / 256, 256>>>(out);
}

// round 4
// speedup vs baseline: 1.2335x; 1.0599x over previous
#include <cuda_runtime.h>

#define NB 32
#define DIM 4096
#define NH 32
#define NKV 8
#define HD 128
#define MAXS 4096
#define POS_NEW 2047
#define NSPLIT 8
#define PPS 256          // positions per split (2048/8)
#define FQKV 6144
#define NDSPLIT 8
#define DRANGE 512       // 4096/8

typedef unsigned long long ull;

__device__ __forceinline__ ull ffma2(ull a, ull b, ull c) {
    ull d;
    asm("fma.rn.f32x2 %0, %1, %2, %3;" : "=l"(d) : "l"(a), "l"(b), "l"(c));
    return d;
}
__device__ __forceinline__ float2 u2f(ull r) {
    float2 v;
    asm("mov.b64 {%0, %1}, %2;" : "=f"(v.x), "=f"(v.y) : "l"(r));
    return v;
}
__device__ __forceinline__ ull f2u(float x, float y) {
    ull r;
    asm("mov.b64 %0, {%1, %2};" : "=l"(r) : "f"(x), "f"(y));
    return r;
}

// ---------------- scratch (device globals; no allocation) ----------------
__device__ __align__(16) float2 g_xt2[(DIM / 2) * NB];
__device__ __align__(16) float  g_part[NDSPLIT * NB * FQKV];
__device__ __align__(16) float  g_qkv[NB * FQKV];
__device__ __align__(16) float  g_kr[NB * NKV * HD];
__device__ __align__(16) float  g_vr[NB * NKV * HD];
__device__ __align__(16) float  g_po[NSPLIT * NB * NH * HD];
__device__ float g_pm[NSPLIT * NB * NH];
__device__ float g_pl[NSPLIT * NB * NH];
__device__ __align__(16) float2 g_at2[(DIM / 2) * NB];

// ---------------- kernel 1: transpose x -> xt2[d2][b] (64 CTAs) ----------------
__global__ void k_transpose(const float* __restrict__ x) {
    __shared__ __align__(16) float t[64][33];
    int d0 = blockIdx.x * 64;
    int tid = threadIdx.x;
#pragma unroll
    for (int k = 0; k < 8; k++) {
        int idx = k * 256 + tid;        // 2048 = 32 b x 64 d
        int bb = idx >> 6, dl = idx & 63;
        t[dl][bb] = x[bb * DIM + d0 + dl];
    }
    __syncthreads();
#pragma unroll
    for (int k = 0; k < 4; k++) {
        int idx = k * 256 + tid;        // 1024 = 32 d2 x 32 b
        int d2l = idx >> 5;
        int b   = idx & 31;
        g_xt2[(d0 / 2 + d2l) * NB + b] = make_float2(t[2 * d2l][b], t[2 * d2l + 1][b]);
    }
}

// ---------------- kernel 2: skinny GEMM, double-buffered, 84-reg budget ------------
// out[b][f] = sum_d xT[d][b] * w[f][d]; partials per d-split into g_part.
__global__ void __launch_bounds__(256, 3)
k_gemm(int mode, const float* __restrict__ w0, const float* __restrict__ w1,
       const float* __restrict__ w2, int F) {
    __shared__ __align__(16) float2 xs[32][32];   // 64 d x 32 b
    __shared__ __align__(16) float  ws[64][64];   // 64 f x 64 d
    int tid = threadIdx.x, lane = tid & 31, warp = tid >> 5;
    int ftile = blockIdx.x * 64;
    int dsplit = blockIdx.y;

    const float2* xt2 = mode ? g_at2 : g_xt2;
    const float* w = w0;
    int frow = ftile;
    if (mode == 0) {
        if (ftile >= 5120)      { w = w2; frow = ftile - 5120; }
        else if (ftile >= 4096) { w = w1; frow = ftile - 4096; }
    }

    const float4* xbase = (const float4*)(xt2 + (size_t)(dsplit * DRANGE / 2) * NB);
    const float* wt = w + (size_t)frow * DIM + dsplit * DRANGE
                        + (size_t)(tid >> 4) * DIM + (tid & 15) * 4;

    // prefetch chunk 0
    float4 px0 = xbase[tid];
    float4 px1 = xbase[tid + 256];
    float4 pw0 = *(const float4*)(wt);
    float4 pw1 = *(const float4*)(wt + 16 * DIM);
    float4 pw2 = *(const float4*)(wt + 32 * DIM);
    float4 pw3 = *(const float4*)(wt + 48 * DIM);

    ull acc[8];
#pragma unroll
    for (int f = 0; f < 8; f++) acc[f] = 0ULL;

    for (int c = 0; c < 8; c++) {
        __syncthreads();
        ((float4*)&xs[0][0])[tid]       = px0;
        ((float4*)&xs[0][0])[tid + 256] = px1;
        {
            float4* wsd = (float4*)ws;
            wsd[tid]       = pw0;
            wsd[tid + 256] = pw1;
            wsd[tid + 512] = pw2;
            wsd[tid + 768] = pw3;
        }
        if (c < 7) {
            const float4* xn = xbase + (c + 1) * 512;
            px0 = xn[tid];
            px1 = xn[tid + 256];
            const float* wn = wt + (c + 1) * 64;
            pw0 = *(const float4*)(wn);
            pw1 = *(const float4*)(wn + 16 * DIM);
            pw2 = *(const float4*)(wn + 32 * DIM);
            pw3 = *(const float4*)(wn + 48 * DIM);
        }
        __syncthreads();
#pragma unroll 4
        for (int j2 = 0; j2 < 16; j2++) {
            ull xa = *(const ull*)&xs[2 * j2][lane];
            ull xb = *(const ull*)&xs[2 * j2 + 1][lane];
            // group 0: f 0..3 (only 4 wv live at once -> no spills)
            {
                ulonglong2 w0r = *(const ulonglong2*)&ws[warp * 8 + 0][4 * j2];
                ulonglong2 w1r = *(const ulonglong2*)&ws[warp * 8 + 1][4 * j2];
                ulonglong2 w2r = *(const ulonglong2*)&ws[warp * 8 + 2][4 * j2];
                ulonglong2 w3r = *(const ulonglong2*)&ws[warp * 8 + 3][4 * j2];
                acc[0] = ffma2(w0r.x, xa, acc[0]); acc[0] = ffma2(w0r.y, xb, acc[0]);
                acc[1] = ffma2(w1r.x, xa, acc[1]); acc[1] = ffma2(w1r.y, xb, acc[1]);
                acc[2] = ffma2(w2r.x, xa, acc[2]); acc[2] = ffma2(w2r.y, xb, acc[2]);
                acc[3] = ffma2(w3r.x, xa, acc[3]); acc[3] = ffma2(w3r.y, xb, acc[3]);
            }
            // group 1: f 4..7
            {
                ulonglong2 w0r = *(const ulonglong2*)&ws[warp * 8 + 4][4 * j2];
                ulonglong2 w1r = *(const ulonglong2*)&ws[warp * 8 + 5][4 * j2];
                ulonglong2 w2r = *(const ulonglong2*)&ws[warp * 8 + 6][4 * j2];
                ulonglong2 w3r = *(const ulonglong2*)&ws[warp * 8 + 7][4 * j2];
                acc[4] = ffma2(w0r.x, xa, acc[4]); acc[4] = ffma2(w0r.y, xb, acc[4]);
                acc[5] = ffma2(w1r.x, xa, acc[5]); acc[5] = ffma2(w1r.y, xb, acc[5]);
                acc[6] = ffma2(w2r.x, xa, acc[6]); acc[6] = ffma2(w2r.y, xb, acc[6]);
                acc[7] = ffma2(w3r.x, xa, acc[7]); acc[7] = ffma2(w3r.y, xb, acc[7]);
            }
        }
    }
#pragma unroll
    for (int f = 0; f < 8; f++) {
        float2 v = u2f(acc[f]);
        g_part[((size_t)dsplit * NB + lane) * F + ftile + warp * 8 + f] = v.x + v.y;
    }
}

// ---------------- kernel 3: reduce QKV partials + fused rope ----------------
__global__ void k_reduce_rope(const float* __restrict__ cosv, const float* __restrict__ sinv) {
    int i2 = blockIdx.x * 256 + threadIdx.x;        // over NB*FQKV/2
    float2 s = make_float2(0.f, 0.f);
#pragma unroll
    for (int k = 0; k < NDSPLIT; k++) {
        float2 v = ((const float2*)g_part)[(size_t)k * (NB * FQKV / 2) + i2];
        s.x += v.x; s.y += v.y;
    }
    int b = i2 / (FQKV / 2), f2 = i2 % (FQKV / 2);
    int f = f2 * 2;
    if (f < 4096) {
        ((float2*)g_qkv)[i2] = s;
    } else {
        int rel = f - 4096;
        int isv = rel >= 1024;
        int rr  = rel & 1023;
        int j   = (rr & 127) >> 1;
        float c = cosv[j], sn = sinv[j];
        float ro = s.x * c - s.y * sn;
        float io = s.x * sn + s.y * c;
        float* dst = isv ? g_vr : g_kr;
        ((float2*)dst)[(size_t)b * (NKV * HD / 2) + (rr >> 1)] = make_float2(ro, io);
    }
}

// ---------------- kernel 3b: float2 reduce for WO output ----------------
__global__ void k_reduce_out(float* __restrict__ out) {
    int i2 = blockIdx.x * 256 + threadIdx.x;        // over NB*DIM/2
    float2 s = make_float2(0.f, 0.f);
#pragma unroll
    for (int k = 0; k < NDSPLIT; k++) {
        float2 v = ((const float2*)g_part)[(size_t)k * (NB * DIM / 2) + i2];
        s.x += v.x; s.y += v.y;
    }
    ((float2*)out)[i2] = s;
}

// ---------------- kernel 4: flash-decode attention ----------------
// grid (NSPLIT, NKV, NB), block 256 (8 warps x 32 positions each)
#define KROW 36
__global__ void __launch_bounds__(256, 4) k_attn(const float* __restrict__ kc,
                                                 const float* __restrict__ vc) {
    __shared__ __align__(16) float  s_ko[8][32 * KROW];  // K tile, reused as O acc
    __shared__ __align__(16) float4 s_q[4][32];
    __shared__ __align__(16) float4 s_p[256];
    __shared__ float s_wm[8][4], s_wl[8][4], s_mb[4];

    int split = blockIdx.x, kvh = blockIdx.y, b = blockIdx.z;
    int tid = threadIdx.x, lane = tid & 31, warp = tid >> 5;
    int p0 = split * PPS + warp * 32;

    if (tid < 128) {
        int h = tid >> 5, j4 = tid & 31;
        s_q[h][j4] = ((const float4*)&g_qkv[b * FQKV + (kvh * 4 + h) * HD])[j4];
    }
    __syncthreads();

    // ---- pass 1: scores; each lane owns position p0+lane ----
    float* kbuf = s_ko[warp];
    int r_ = lane >> 3, jj = lane & 7;
    const float* knew = &g_kr[(b * NKV + kvh) * HD];

    float4 pre[8];
#pragma unroll
    for (int i = 0; i < 8; i++) {
        int r = i * 4 + r_;
        int pos = p0 + r;
        const float* src = (pos == POS_NEW) ? knew
                         : kc + (((size_t)b * MAXS + pos) * NKV + kvh) * HD;
        pre[i] = *(const float4*)(src + jj * 4);
    }

    ull acc[4];
#pragma unroll
    for (int h = 0; h < 4; h++) acc[h] = 0ULL;

#pragma unroll
    for (int c = 0; c < 4; c++) {
#pragma unroll
        for (int i = 0; i < 8; i++) {
            int r = i * 4 + r_;
            *(float4*)&kbuf[r * KROW + jj * 4] = pre[i];
        }
        if (c < 3) {
#pragma unroll
            for (int i = 0; i < 8; i++) {
                int r = i * 4 + r_;
                int pos = p0 + r;
                const float* src = (pos == POS_NEW) ? knew
                                 : kc + (((size_t)b * MAXS + pos) * NKV + kvh) * HD;
                pre[i] = *(const float4*)(src + (c + 1) * 32 + jj * 4);
            }
        }
        __syncwarp();
#pragma unroll
        for (int j4 = 0; j4 < 8; j4++) {
            ulonglong2 k2 = *(const ulonglong2*)&kbuf[lane * KROW + j4 * 4];
#pragma unroll
            for (int h = 0; h < 4; h++) {
                ulonglong2 q2 = *(const ulonglong2*)&s_q[h][c * 8 + j4];
                acc[h] = ffma2(q2.x, k2.x, acc[h]);
                acc[h] = ffma2(q2.y, k2.y, acc[h]);
            }
        }
        __syncwarp();
    }

    const float scale = 0.08838834764831845f;  // 1/sqrt(128)
    float sc[4], m[4];
#pragma unroll
    for (int h = 0; h < 4; h++) {
        float2 t = u2f(acc[h]);
        sc[h] = (t.x + t.y) * scale;
        m[h] = sc[h];
    }
#pragma unroll
    for (int off = 16; off > 0; off >>= 1) {
#pragma unroll
        for (int h = 0; h < 4; h++)
            m[h] = fmaxf(m[h], __shfl_xor_sync(0xffffffffu, m[h], off));
    }
    if (lane == 0) {
#pragma unroll
        for (int h = 0; h < 4; h++) s_wm[warp][h] = m[h];
    }
    __syncthreads();

    float mb[4];
#pragma unroll
    for (int h = 0; h < 4; h++) {
        float v = s_wm[0][h];
#pragma unroll
        for (int ww = 1; ww < 8; ww++) v = fmaxf(v, s_wm[ww][h]);
        mb[h] = v;
    }
    float p[4], l[4];
#pragma unroll
    for (int h = 0; h < 4; h++) {
        p[h] = __expf(sc[h] - mb[h]);
        l[h] = p[h];
    }
    s_p[tid] = make_float4(p[0], p[1], p[2], p[3]);
#pragma unroll
    for (int off = 16; off > 0; off >>= 1) {
#pragma unroll
        for (int h = 0; h < 4; h++)
            l[h] += __shfl_xor_sync(0xffffffffu, l[h], off);
    }
    if (lane == 0) {
#pragma unroll
        for (int h = 0; h < 4; h++) s_wl[warp][h] = l[h];
    }
    if (tid < 4) s_mb[tid] = mb[tid];
    __syncthreads();

    // ---- pass 3: O += p * V, rotating 4-deep register prefetch ----
    const float* vnew = &g_vr[(b * NKV + kvh) * HD];
    ull a01[4], a23[4];
#pragma unroll
    for (int h = 0; h < 4; h++) { a01[h] = 0ULL; a23[h] = 0ULL; }

    float4 pv[4];
#pragma unroll
    for (int k = 0; k < 4; k++) {
        int pos = p0 + k;
        const float* vrow = (pos == POS_NEW) ? vnew
                          : vc + (((size_t)b * MAXS + pos) * NKV + kvh) * HD;
        pv[k] = ((const float4*)vrow)[lane];
    }
#pragma unroll
    for (int g = 0; g < 8; g++) {
#pragma unroll
        for (int k = 0; k < 4; k++) {
            float4 cur = pv[k];
            if (g < 7) {
                int pos = p0 + (g + 1) * 4 + k;
                const float* vrow = (pos == POS_NEW) ? vnew
                                  : vc + (((size_t)b * MAXS + pos) * NKV + kvh) * HD;
                pv[k] = ((const float4*)vrow)[lane];
            }
            ulonglong2 vv = *(const ulonglong2*)&cur;
            float4 pp = s_p[warp * 32 + g * 4 + k];
            ull pu;
            pu = f2u(pp.x, pp.x); a01[0] = ffma2(pu, vv.x, a01[0]); a23[0] = ffma2(pu, vv.y, a23[0]);
            pu = f2u(pp.y, pp.y); a01[1] = ffma2(pu, vv.x, a01[1]); a23[1] = ffma2(pu, vv.y, a23[1]);
            pu = f2u(pp.z, pp.z); a01[2] = ffma2(pu, vv.x, a01[2]); a23[2] = ffma2(pu, vv.y, a23[2]);
            pu = f2u(pp.w, pp.w); a01[3] = ffma2(pu, vv.x, a01[3]); a23[3] = ffma2(pu, vv.y, a23[3]);
        }
    }
    float* os = &s_ko[0][0];
#pragma unroll
    for (int h = 0; h < 4; h++) {
        float2 lo = u2f(a01[h]), hi = u2f(a23[h]);
        *(float4*)&os[(warp * 4 + h) * HD + lane * 4] = make_float4(lo.x, lo.y, hi.x, hi.y);
    }
    __syncthreads();

    // ---- final: cross-warp sum, write partials ----
#pragma unroll
    for (int k = 0; k < 2; k++) {
        int o = tid + k * 256;
        int h = o >> 7, d = o & 127;
        float s = 0.f;
#pragma unroll
        for (int ww = 0; ww < 8; ww++) s += os[(ww * 4 + h) * HD + d];
        g_po[(((size_t)split * NB + b) * NH + kvh * 4 + h) * HD + d] = s;
    }
    if (tid < 4) {
        float gl = 0.f;
#pragma unroll
        for (int ww = 0; ww < 8; ww++) gl += s_wl[ww][tid];
        g_pl[((size_t)split * NB + b) * NH + kvh * 4 + tid] = gl;
        g_pm[((size_t)split * NB + b) * NH + kvh * 4 + tid] = s_mb[tid];
    }
}

// ---------------- kernel 6: combine splits, write attn transposed ----------------
__global__ void k_combine() {
    int gh = blockIdx.x, b = blockIdx.y;
    int t = threadIdx.x;
    __shared__ float s_w[NSPLIT];
    __shared__ float s_gl;
    if (t == 0) {
        float ms[NSPLIT];
        float gm = -1e30f;
#pragma unroll
        for (int s = 0; s < NSPLIT; s++) {
            ms[s] = g_pm[((size_t)s * NB + b) * NH + gh];
            gm = fmaxf(gm, ms[s]);
        }
        float gl = 0.f;
#pragma unroll
        for (int s = 0; s < NSPLIT; s++) {
            float wv = __expf(ms[s] - gm);
            s_w[s] = wv;
            gl += wv * g_pl[((size_t)s * NB + b) * NH + gh];
        }
        s_gl = gl;
    }
    __syncthreads();
    float inv = 1.0f / s_gl;
    float o0 = 0.f, o1 = 0.f;
#pragma unroll
    for (int s = 0; s < NSPLIT; s++) {
        const float* po = &g_po[(((size_t)s * NB + b) * NH + gh) * HD];
        float wv = s_w[s];
        o0 += wv * po[2 * t];
        o1 += wv * po[2 * t + 1];
    }
    g_at2[(size_t)(gh * 64 + t) * NB + b] = make_float2(o0 * inv, o1 * inv);
}

// ---------------- launcher ----------------
extern "C" void kernel_launch(void* const* d_in, const int* in_sizes, int n_in,
                              void* d_out, int out_size) {
    const float* x  = (const float*)d_in[0];
    const float* tc = (const float*)d_in[2];
    const float* ts = (const float*)d_in[3];
    const float* wq = (const float*)d_in[4];
    const float* wk = (const float*)d_in[5];
    const float* wv = (const float*)d_in[6];
    const float* wo = (const float*)d_in[7];
    const float* kc = (const float*)d_in[8];
    const float* vc = (const float*)d_in[9];
    float* out = (float*)d_out;

    k_transpose<<<64, 256>>>(x);
    k_gemm<<<dim3(FQKV / 64, NDSPLIT), 256>>>(0, wq, wk, wv, FQKV);
    k_reduce_rope<<<NB * FQKV / 2 / 256, 256>>>(tc, ts);
    k_attn<<<dim3(NSPLIT, NKV, NB), 256>>>(kc, vc);
    k_combine<<<dim3(NH, NB), 64>>>();
    k_gemm<<<dim3(DIM / 64, NDSPLIT), 256>>>(1, wo, nullptr, nullptr, DIM);
    k_reduce_out<<<NB * DIM / 2 / 256, 256>>>(out);
}

// round 5
// speedup vs baseline: 1.2978x; 1.0521x over previous
#include <cuda_runtime.h>

#define NB 32
#define DIM 4096
#define NH 32
#define NKV 8
#define HD 128
#define MAXS 4096
#define POS_NEW 2047
#define NSPLIT 8
#define PPS 256          // positions per split (2048/8)
#define FQKV 6144
#define NDSPLIT 8
#define DRANGE 512       // 4096/8

typedef unsigned long long ull;

__device__ __forceinline__ ull ffma2(ull a, ull b, ull c) {
    ull d;
    asm("fma.rn.f32x2 %0, %1, %2, %3;" : "=l"(d) : "l"(a), "l"(b), "l"(c));
    return d;
}
__device__ __forceinline__ float2 u2f(ull r) {
    float2 v;
    asm("mov.b64 {%0, %1}, %2;" : "=f"(v.x), "=f"(v.y) : "l"(r));
    return v;
}
__device__ __forceinline__ ull f2u(float x, float y) {
    ull r;
    asm("mov.b64 %0, {%1, %2};" : "=l"(r) : "f"(x), "f"(y));
    return r;
}
__device__ __forceinline__ unsigned smem_u32(const void* p) {
    return (unsigned)__cvta_generic_to_shared(p);
}
#define CP16(dst, src) \
    asm volatile("cp.async.cg.shared.global [%0], [%1], 16;" :: "r"(dst), "l"(src))
#define CP_COMMIT() asm volatile("cp.async.commit_group;")
#define CP_WAIT1()  asm volatile("cp.async.wait_group 1;")
#define CP_WAIT0()  asm volatile("cp.async.wait_group 0;")

// ---------------- scratch (device globals; no allocation) ----------------
__device__ __align__(16) float2 g_xt2[(DIM / 2) * NB];
__device__ __align__(16) float  g_part[NDSPLIT * NB * FQKV];
__device__ __align__(16) float  g_qkv[NB * FQKV];
__device__ __align__(16) float  g_kr[NB * NKV * HD];
__device__ __align__(16) float  g_vr[NB * NKV * HD];
__device__ __align__(16) float  g_po[NSPLIT * NB * NH * HD];
__device__ float g_pm[NSPLIT * NB * NH];
__device__ float g_pl[NSPLIT * NB * NH];
__device__ __align__(16) float2 g_at2[(DIM / 2) * NB];

// ---------------- kernel 1: transpose x -> xt2[d2][b] (64 CTAs) ----------------
__global__ void k_transpose(const float* __restrict__ x) {
    __shared__ __align__(16) float t[64][33];
    int d0 = blockIdx.x * 64;
    int tid = threadIdx.x;
#pragma unroll
    for (int k = 0; k < 8; k++) {
        int idx = k * 256 + tid;        // 2048 = 32 b x 64 d
        int bb = idx >> 6, dl = idx & 63;
        t[dl][bb] = x[bb * DIM + d0 + dl];
    }
    __syncthreads();
#pragma unroll
    for (int k = 0; k < 4; k++) {
        int idx = k * 256 + tid;        // 1024 = 32 d2 x 32 b
        int d2l = idx >> 5;
        int b   = idx & 31;
        g_xt2[(d0 / 2 + d2l) * NB + b] = make_float2(t[2 * d2l][b], t[2 * d2l + 1][b]);
    }
}

// ---------------- kernel 2: skinny GEMM, cp.async double-buffered ----------------
// out[b][f] = sum_d xT[d][b] * w[f][d]; partials per d-split into g_part.
__global__ void __launch_bounds__(256, 4)
k_gemm(int mode, const float* __restrict__ w0, const float* __restrict__ w1,
       const float* __restrict__ w2, int F) {
    __shared__ __align__(16) float2 xs[2][32][32];   // 2 x 8KB  (64 d x 32 b)
    __shared__ __align__(16) float  ws[2][64][64];   // 2 x 16KB (64 f x 64 d)
    int tid = threadIdx.x, lane = tid & 31, warp = tid >> 5;
    int ftile = blockIdx.x * 64;
    int dsplit = blockIdx.y;

    const float2* xt2 = mode ? g_at2 : g_xt2;
    const float* w = w0;
    int frow = ftile;
    if (mode == 0) {
        if (ftile >= 5120)      { w = w2; frow = ftile - 5120; }
        else if (ftile >= 4096) { w = w1; frow = ftile - 4096; }
    }

    const float4* xbase = (const float4*)(xt2 + (size_t)(dsplit * DRANGE / 2) * NB);
    const float* wt = w + (size_t)frow * DIM + dsplit * DRANGE
                        + (size_t)(tid >> 4) * DIM + (tid & 15) * 4;

    // async-stage chunk c into buffer s
    unsigned xd0 = smem_u32(&xs[0][0][0]) + tid * 16;
    unsigned xd1 = smem_u32(&xs[1][0][0]) + tid * 16;
    unsigned wd0 = smem_u32(&ws[0][0][0]) + tid * 16;
    unsigned wd1 = smem_u32(&ws[1][0][0]) + tid * 16;

#define STAGE(c, s) do {                                   \
        unsigned xd = (s) ? xd1 : xd0;                     \
        unsigned wd = (s) ? wd1 : wd0;                     \
        const float4* xn = xbase + (c) * 512;              \
        CP16(xd,            xn + tid);                     \
        CP16(xd + 256 * 16, xn + tid + 256);               \
        const float* wn = wt + (c) * 64;                   \
        CP16(wd,            wn);                           \
        CP16(wd + 256 * 16, wn + 16 * DIM);                \
        CP16(wd + 512 * 16, wn + 32 * DIM);                \
        CP16(wd + 768 * 16, wn + 48 * DIM);                \
    } while (0)

    STAGE(0, 0); CP_COMMIT();
    STAGE(1, 1); CP_COMMIT();

    ull acc[8];
#pragma unroll
    for (int f = 0; f < 8; f++) acc[f] = 0ULL;

    for (int c = 0; c < 8; c++) {
        int s = c & 1;
        if (c < 7) CP_WAIT1(); else CP_WAIT0();
        __syncthreads();
#pragma unroll 4
        for (int j2 = 0; j2 < 16; j2++) {
            ull xa = *(const ull*)&xs[s][2 * j2][lane];
            ull xb = *(const ull*)&xs[s][2 * j2 + 1][lane];
            {
                ulonglong2 w0r = *(const ulonglong2*)&ws[s][warp * 8 + 0][4 * j2];
                ulonglong2 w1r = *(const ulonglong2*)&ws[s][warp * 8 + 1][4 * j2];
                ulonglong2 w2r = *(const ulonglong2*)&ws[s][warp * 8 + 2][4 * j2];
                ulonglong2 w3r = *(const ulonglong2*)&ws[s][warp * 8 + 3][4 * j2];
                acc[0] = ffma2(w0r.x, xa, acc[0]); acc[0] = ffma2(w0r.y, xb, acc[0]);
                acc[1] = ffma2(w1r.x, xa, acc[1]); acc[1] = ffma2(w1r.y, xb, acc[1]);
                acc[2] = ffma2(w2r.x, xa, acc[2]); acc[2] = ffma2(w2r.y, xb, acc[2]);
                acc[3] = ffma2(w3r.x, xa, acc[3]); acc[3] = ffma2(w3r.y, xb, acc[3]);
            }
            {
                ulonglong2 w0r = *(const ulonglong2*)&ws[s][warp * 8 + 4][4 * j2];
                ulonglong2 w1r = *(const ulonglong2*)&ws[s][warp * 8 + 5][4 * j2];
                ulonglong2 w2r = *(const ulonglong2*)&ws[s][warp * 8 + 6][4 * j2];
                ulonglong2 w3r = *(const ulonglong2*)&ws[s][warp * 8 + 7][4 * j2];
                acc[4] = ffma2(w0r.x, xa, acc[4]); acc[4] = ffma2(w0r.y, xb, acc[4]);
                acc[5] = ffma2(w1r.x, xa, acc[5]); acc[5] = ffma2(w1r.y, xb, acc[5]);
                acc[6] = ffma2(w2r.x, xa, acc[6]); acc[6] = ffma2(w2r.y, xb, acc[6]);
                acc[7] = ffma2(w3r.x, xa, acc[7]); acc[7] = ffma2(w3r.y, xb, acc[7]);
            }
        }
        __syncthreads();
        if (c + 2 < 8) { STAGE(c + 2, s); CP_COMMIT(); }
    }
#undef STAGE

#pragma unroll
    for (int f = 0; f < 8; f++) {
        float2 v = u2f(acc[f]);
        g_part[((size_t)dsplit * NB + lane) * F + ftile + warp * 8 + f] = v.x + v.y;
    }
}

// ---------------- kernel 3: reduce QKV partials + fused rope ----------------
__global__ void k_reduce_rope(const float* __restrict__ cosv, const float* __restrict__ sinv) {
    int i2 = blockIdx.x * 256 + threadIdx.x;        // over NB*FQKV/2
    float2 s = make_float2(0.f, 0.f);
#pragma unroll
    for (int k = 0; k < NDSPLIT; k++) {
        float2 v = ((const float2*)g_part)[(size_t)k * (NB * FQKV / 2) + i2];
        s.x += v.x; s.y += v.y;
    }
    int b = i2 / (FQKV / 2), f2 = i2 % (FQKV / 2);
    int f = f2 * 2;
    if (f < 4096) {
        ((float2*)g_qkv)[i2] = s;
    } else {
        int rel = f - 4096;
        int isv = rel >= 1024;
        int rr  = rel & 1023;
        int j   = (rr & 127) >> 1;
        float c = cosv[j], sn = sinv[j];
        float ro = s.x * c - s.y * sn;
        float io = s.x * sn + s.y * c;
        float* dst = isv ? g_vr : g_kr;
        ((float2*)dst)[(size_t)b * (NKV * HD / 2) + (rr >> 1)] = make_float2(ro, io);
    }
}

// ---------------- kernel 3b: float2 reduce for WO output ----------------
__global__ void k_reduce_out(float* __restrict__ out) {
    int i2 = blockIdx.x * 256 + threadIdx.x;        // over NB*DIM/2
    float2 s = make_float2(0.f, 0.f);
#pragma unroll
    for (int k = 0; k < NDSPLIT; k++) {
        float2 v = ((const float2*)g_part)[(size_t)k * (NB * DIM / 2) + i2];
        s.x += v.x; s.y += v.y;
    }
    ((float2*)out)[i2] = s;
}

// ---------------- kernel 4: flash-decode attention ----------------
// grid (NSPLIT, NKV, NB), block 256 (8 warps x 32 positions each)
#define KROW 36
__global__ void __launch_bounds__(256, 4) k_attn(const float* __restrict__ kc,
                                                 const float* __restrict__ vc) {
    __shared__ __align__(16) float  s_ko[8][32 * KROW];  // K tile, reused as O acc
    __shared__ __align__(16) float4 s_q[4][32];
    __shared__ __align__(16) float4 s_p[256];
    __shared__ float s_wm[8][4], s_wl[8][4], s_mb[4];

    int split = blockIdx.x, kvh = blockIdx.y, b = blockIdx.z;
    int tid = threadIdx.x, lane = tid & 31, warp = tid >> 5;
    int p0 = split * PPS + warp * 32;

    if (tid < 128) {
        int h = tid >> 5, j4 = tid & 31;
        s_q[h][j4] = ((const float4*)&g_qkv[b * FQKV + (kvh * 4 + h) * HD])[j4];
    }
    __syncthreads();

    // ---- pass 1: scores; each lane owns position p0+lane ----
    float* kbuf = s_ko[warp];
    int r_ = lane >> 3, jj = lane & 7;
    const float* knew = &g_kr[(b * NKV + kvh) * HD];

    float4 pre[8];
#pragma unroll
    for (int i = 0; i < 8; i++) {
        int r = i * 4 + r_;
        int pos = p0 + r;
        const float* src = (pos == POS_NEW) ? knew
                         : kc + (((size_t)b * MAXS + pos) * NKV + kvh) * HD;
        pre[i] = *(const float4*)(src + jj * 4);
    }

    ull acc[4];
#pragma unroll
    for (int h = 0; h < 4; h++) acc[h] = 0ULL;

#pragma unroll
    for (int c = 0; c < 4; c++) {
#pragma unroll
        for (int i = 0; i < 8; i++) {
            int r = i * 4 + r_;
            *(float4*)&kbuf[r * KROW + jj * 4] = pre[i];
        }
        if (c < 3) {
#pragma unroll
            for (int i = 0; i < 8; i++) {
                int r = i * 4 + r_;
                int pos = p0 + r;
                const float* src = (pos == POS_NEW) ? knew
                                 : kc + (((size_t)b * MAXS + pos) * NKV + kvh) * HD;
                pre[i] = *(const float4*)(src + (c + 1) * 32 + jj * 4);
            }
        }
        __syncwarp();
#pragma unroll
        for (int j4 = 0; j4 < 8; j4++) {
            ulonglong2 k2 = *(const ulonglong2*)&kbuf[lane * KROW + j4 * 4];
#pragma unroll
            for (int h = 0; h < 4; h++) {
                ulonglong2 q2 = *(const ulonglong2*)&s_q[h][c * 8 + j4];
                acc[h] = ffma2(q2.x, k2.x, acc[h]);
                acc[h] = ffma2(q2.y, k2.y, acc[h]);
            }
        }
        __syncwarp();
    }

    const float scale = 0.08838834764831845f;  // 1/sqrt(128)
    float sc[4], m[4];
#pragma unroll
    for (int h = 0; h < 4; h++) {
        float2 t = u2f(acc[h]);
        sc[h] = (t.x + t.y) * scale;
        m[h] = sc[h];
    }
#pragma unroll
    for (int off = 16; off > 0; off >>= 1) {
#pragma unroll
        for (int h = 0; h < 4; h++)
            m[h] = fmaxf(m[h], __shfl_xor_sync(0xffffffffu, m[h], off));
    }
    if (lane == 0) {
#pragma unroll
        for (int h = 0; h < 4; h++) s_wm[warp][h] = m[h];
    }
    __syncthreads();

    float mb[4];
#pragma unroll
    for (int h = 0; h < 4; h++) {
        float v = s_wm[0][h];
#pragma unroll
        for (int ww = 1; ww < 8; ww++) v = fmaxf(v, s_wm[ww][h]);
        mb[h] = v;
    }
    float p[4], l[4];
#pragma unroll
    for (int h = 0; h < 4; h++) {
        p[h] = __expf(sc[h] - mb[h]);
        l[h] = p[h];
    }
    s_p[tid] = make_float4(p[0], p[1], p[2], p[3]);
#pragma unroll
    for (int off = 16; off > 0; off >>= 1) {
#pragma unroll
        for (int h = 0; h < 4; h++)
            l[h] += __shfl_xor_sync(0xffffffffu, l[h], off);
    }
    if (lane == 0) {
#pragma unroll
        for (int h = 0; h < 4; h++) s_wl[warp][h] = l[h];
    }
    if (tid < 4) s_mb[tid] = mb[tid];
    __syncthreads();

    // ---- pass 3: O += p * V, rotating 4-deep register prefetch ----
    const float* vnew = &g_vr[(b * NKV + kvh) * HD];
    ull a01[4], a23[4];
#pragma unroll
    for (int h = 0; h < 4; h++) { a01[h] = 0ULL; a23[h] = 0ULL; }

    float4 pv[4];
#pragma unroll
    for (int k = 0; k < 4; k++) {
        int pos = p0 + k;
        const float* vrow = (pos == POS_NEW) ? vnew
                          : vc + (((size_t)b * MAXS + pos) * NKV + kvh) * HD;
        pv[k] = ((const float4*)vrow)[lane];
    }
#pragma unroll
    for (int g = 0; g < 8; g++) {
#pragma unroll
        for (int k = 0; k < 4; k++) {
            float4 cur = pv[k];
            if (g < 7) {
                int pos = p0 + (g + 1) * 4 + k;
                const float* vrow = (pos == POS_NEW) ? vnew
                                  : vc + (((size_t)b * MAXS + pos) * NKV + kvh) * HD;
                pv[k] = ((const float4*)vrow)[lane];
            }
            ulonglong2 vv = *(const ulonglong2*)&cur;
            float4 pp = s_p[warp * 32 + g * 4 + k];
            ull pu;
            pu = f2u(pp.x, pp.x); a01[0] = ffma2(pu, vv.x, a01[0]); a23[0] = ffma2(pu, vv.y, a23[0]);
            pu = f2u(pp.y, pp.y); a01[1] = ffma2(pu, vv.x, a01[1]); a23[1] = ffma2(pu, vv.y, a23[1]);
            pu = f2u(pp.z, pp.z); a01[2] = ffma2(pu, vv.x, a01[2]); a23[2] = ffma2(pu, vv.y, a23[2]);
            pu = f2u(pp.w, pp.w); a01[3] = ffma2(pu, vv.x, a01[3]); a23[3] = ffma2(pu, vv.y, a23[3]);
        }
    }
    float* os = &s_ko[0][0];
#pragma unroll
    for (int h = 0; h < 4; h++) {
        float2 lo = u2f(a01[h]), hi = u2f(a23[h]);
        *(float4*)&os[(warp * 4 + h) * HD + lane * 4] = make_float4(lo.x, lo.y, hi.x, hi.y);
    }
    __syncthreads();

    // ---- final: cross-warp sum, write partials ----
#pragma unroll
    for (int k = 0; k < 2; k++) {
        int o = tid + k * 256;
        int h = o >> 7, d = o & 127;
        float s = 0.f;
#pragma unroll
        for (int ww = 0; ww < 8; ww++) s += os[(ww * 4 + h) * HD + d];
        g_po[(((size_t)split * NB + b) * NH + kvh * 4 + h) * HD + d] = s;
    }
    if (tid < 4) {
        float gl = 0.f;
#pragma unroll
        for (int ww = 0; ww < 8; ww++) gl += s_wl[ww][tid];
        g_pl[((size_t)split * NB + b) * NH + kvh * 4 + tid] = gl;
        g_pm[((size_t)split * NB + b) * NH + kvh * 4 + tid] = s_mb[tid];
    }
}

// ---------------- kernel 6: combine splits, write attn transposed ----------------
__global__ void k_combine() {
    int gh = blockIdx.x, b = blockIdx.y;
    int t = threadIdx.x;
    __shared__ float s_w[NSPLIT];
    __shared__ float s_gl;
    if (t == 0) {
        float ms[NSPLIT];
        float gm = -1e30f;
#pragma unroll
        for (int s = 0; s < NSPLIT; s++) {
            ms[s] = g_pm[((size_t)s * NB + b) * NH + gh];
            gm = fmaxf(gm, ms[s]);
        }
        float gl = 0.f;
#pragma unroll
        for (int s = 0; s < NSPLIT; s++) {
            float wv = __expf(ms[s] - gm);
            s_w[s] = wv;
            gl += wv * g_pl[((size_t)s * NB + b) * NH + gh];
        }
        s_gl = gl;
    }
    __syncthreads();
    float inv = 1.0f / s_gl;
    float o0 = 0.f, o1 = 0.f;
#pragma unroll
    for (int s = 0; s < NSPLIT; s++) {
        const float* po = &g_po[(((size_t)s * NB + b) * NH + gh) * HD];
        float wv = s_w[s];
        o0 += wv * po[2 * t];
        o1 += wv * po[2 * t + 1];
    }
    g_at2[(size_t)(gh * 64 + t) * NB + b] = make_float2(o0 * inv, o1 * inv);
}

// ---------------- launcher ----------------
extern "C" void kernel_launch(void* const* d_in, const int* in_sizes, int n_in,
                              void* d_out, int out_size) {
    const float* x  = (const float*)d_in[0];
    const float* tc = (const float*)d_in[2];
    const float* ts = (const float*)d_in[3];
    const float* wq = (const float*)d_in[4];
    const float* wk = (const float*)d_in[5];
    const float* wv = (const float*)d_in[6];
    const float* wo = (const float*)d_in[7];
    const float* kc = (const float*)d_in[8];
    const float* vc = (const float*)d_in[9];
    float* out = (float*)d_out;

    k_transpose<<<64, 256>>>(x);
    k_gemm<<<dim3(FQKV / 64, NDSPLIT), 256>>>(0, wq, wk, wv, FQKV);
    k_reduce_rope<<<NB * FQKV / 2 / 256, 256>>>(tc, ts);
    k_attn<<<dim3(NSPLIT, NKV, NB), 256>>>(kc, vc);
    k_combine<<<dim3(NH, NB), 64>>>();
    k_gemm<<<dim3(DIM / 64, NDSPLIT), 256>>>(1, wo, nullptr, nullptr, DIM);
    k_reduce_out<<<NB * DIM / 2 / 256, 256>>>(out);
}

// round 6
// speedup vs baseline: 1.4384x; 1.1084x over previous
#include <cuda_runtime.h>

#define NB 32
#define DIM 4096
#define NH 32
#define NKV 8
#define HD 128
#define MAXS 4096
#define POS_NEW 2047
#define NSPLIT 16
#define PPS 128          // positions per split (2048/16)
#define FQKV 6144
#define NDSPLIT 16
#define DRANGE 256       // 4096/16

typedef unsigned long long ull;

__device__ __forceinline__ ull ffma2(ull a, ull b, ull c) {
    ull d;
    asm("fma.rn.f32x2 %0, %1, %2, %3;" : "=l"(d) : "l"(a), "l"(b), "l"(c));
    return d;
}
__device__ __forceinline__ float2 u2f(ull r) {
    float2 v;
    asm("mov.b64 {%0, %1}, %2;" : "=f"(v.x), "=f"(v.y) : "l"(r));
    return v;
}
__device__ __forceinline__ ull f2u(float x, float y) {
    ull r;
    asm("mov.b64 %0, {%1, %2};" : "=l"(r) : "f"(x), "f"(y));
    return r;
}
__device__ __forceinline__ unsigned smem_u32(const void* p) {
    return (unsigned)__cvta_generic_to_shared(p);
}
#define CP16(dst, src) \
    asm volatile("cp.async.cg.shared.global [%0], [%1], 16;" :: "r"(dst), "l"(src))
#define CP_COMMIT() asm volatile("cp.async.commit_group;")
#define CP_WAIT1()  asm volatile("cp.async.wait_group 1;")
#define CP_WAIT0()  asm volatile("cp.async.wait_group 0;")

// ---------------- scratch (device globals; no allocation) ----------------
__device__ __align__(16) float2 g_xt2[(DIM / 2) * NB];
__device__ __align__(16) float  g_part[NDSPLIT * FQKV * NB];   // P[k][f][b]
__device__ __align__(16) float  g_qkv[NB * FQKV];
__device__ __align__(16) float  g_kr[NB * NKV * HD];
__device__ __align__(16) float  g_vr[NB * NKV * HD];
__device__ __align__(16) float  g_po[NSPLIT * NB * NH * HD];
__device__ float g_pm[NSPLIT * NB * NH];
__device__ float g_pl[NSPLIT * NB * NH];
__device__ __align__(16) float2 g_at2[(DIM / 2) * NB];

// ---------------- kernel 1: transpose x -> xt2[d2][b] (64 CTAs) ----------------
__global__ void k_transpose(const float* __restrict__ x) {
    __shared__ __align__(16) float t[64][33];
    int d0 = blockIdx.x * 64;
    int tid = threadIdx.x;
#pragma unroll
    for (int k = 0; k < 8; k++) {
        int idx = k * 256 + tid;
        int bb = idx >> 6, dl = idx & 63;
        t[dl][bb] = x[bb * DIM + d0 + dl];
    }
    __syncthreads();
#pragma unroll
    for (int k = 0; k < 4; k++) {
        int idx = k * 256 + tid;
        int d2l = idx >> 5;
        int b   = idx & 31;
        g_xt2[(d0 / 2 + d2l) * NB + b] = make_float2(t[2 * d2l][b], t[2 * d2l + 1][b]);
    }
}

// ---------------- kernel 2: skinny GEMM, cp.async double-buffered ----------------
// out[b][f] = sum_d xT[d][b] * w[f][d]; partials P[k][f][b] coalesced.
__global__ void __launch_bounds__(256, 4)
k_gemm(int mode, const float* __restrict__ w0, const float* __restrict__ w1,
       const float* __restrict__ w2, int F) {
    __shared__ __align__(16) float2 xs[2][32][32];   // 2 x 8KB  (64 d x 32 b)
    __shared__ __align__(16) float  ws[2][64][64];   // 2 x 16KB (64 f x 64 d)
    int tid = threadIdx.x, lane = tid & 31, warp = tid >> 5;
    int ftile = blockIdx.x * 64;
    int dsplit = blockIdx.y;

    const float2* xt2 = mode ? g_at2 : g_xt2;
    const float* w = w0;
    int frow = ftile;
    if (mode == 0) {
        if (ftile >= 5120)      { w = w2; frow = ftile - 5120; }
        else if (ftile >= 4096) { w = w1; frow = ftile - 4096; }
    }

    const float4* xbase = (const float4*)(xt2 + (size_t)(dsplit * DRANGE / 2) * NB);
    const float* wt = w + (size_t)frow * DIM + dsplit * DRANGE
                        + (size_t)(tid >> 4) * DIM + (tid & 15) * 4;

    unsigned xd0 = smem_u32(&xs[0][0][0]) + tid * 16;
    unsigned xd1 = smem_u32(&xs[1][0][0]) + tid * 16;
    unsigned wd0 = smem_u32(&ws[0][0][0]) + tid * 16;
    unsigned wd1 = smem_u32(&ws[1][0][0]) + tid * 16;

#define STAGE(c, s) do {                                   \
        unsigned xd = (s) ? xd1 : xd0;                     \
        unsigned wd = (s) ? wd1 : wd0;                     \
        const float4* xn = xbase + (c) * 512;              \
        CP16(xd,            xn + tid);                     \
        CP16(xd + 256 * 16, xn + tid + 256);               \
        const float* wn = wt + (c) * 64;                   \
        CP16(wd,            wn);                           \
        CP16(wd + 256 * 16, wn + 16 * DIM);                \
        CP16(wd + 512 * 16, wn + 32 * DIM);                \
        CP16(wd + 768 * 16, wn + 48 * DIM);                \
    } while (0)

    STAGE(0, 0); CP_COMMIT();
    STAGE(1, 1); CP_COMMIT();

    ull acc[8];
#pragma unroll
    for (int f = 0; f < 8; f++) acc[f] = 0ULL;

    const int NCH = DRANGE / 64;   // 4
    for (int c = 0; c < NCH; c++) {
        int s = c & 1;
        if (c < NCH - 1) CP_WAIT1(); else CP_WAIT0();
        __syncthreads();
#pragma unroll 4
        for (int j2 = 0; j2 < 16; j2++) {
            ull xa = *(const ull*)&xs[s][2 * j2][lane];
            ull xb = *(const ull*)&xs[s][2 * j2 + 1][lane];
            {
                ulonglong2 w0r = *(const ulonglong2*)&ws[s][warp * 8 + 0][4 * j2];
                ulonglong2 w1r = *(const ulonglong2*)&ws[s][warp * 8 + 1][4 * j2];
                ulonglong2 w2r = *(const ulonglong2*)&ws[s][warp * 8 + 2][4 * j2];
                ulonglong2 w3r = *(const ulonglong2*)&ws[s][warp * 8 + 3][4 * j2];
                acc[0] = ffma2(w0r.x, xa, acc[0]); acc[0] = ffma2(w0r.y, xb, acc[0]);
                acc[1] = ffma2(w1r.x, xa, acc[1]); acc[1] = ffma2(w1r.y, xb, acc[1]);
                acc[2] = ffma2(w2r.x, xa, acc[2]); acc[2] = ffma2(w2r.y, xb, acc[2]);
                acc[3] = ffma2(w3r.x, xa, acc[3]); acc[3] = ffma2(w3r.y, xb, acc[3]);
            }
            {
                ulonglong2 w0r = *(const ulonglong2*)&ws[s][warp * 8 + 4][4 * j2];
                ulonglong2 w1r = *(const ulonglong2*)&ws[s][warp * 8 + 5][4 * j2];
                ulonglong2 w2r = *(const ulonglong2*)&ws[s][warp * 8 + 6][4 * j2];
                ulonglong2 w3r = *(const ulonglong2*)&ws[s][warp * 8 + 7][4 * j2];
                acc[4] = ffma2(w0r.x, xa, acc[4]); acc[4] = ffma2(w0r.y, xb, acc[4]);
                acc[5] = ffma2(w1r.x, xa, acc[5]); acc[5] = ffma2(w1r.y, xb, acc[5]);
                acc[6] = ffma2(w2r.x, xa, acc[6]); acc[6] = ffma2(w2r.y, xb, acc[6]);
                acc[7] = ffma2(w3r.x, xa, acc[7]); acc[7] = ffma2(w3r.y, xb, acc[7]);
            }
        }
        __syncthreads();
        if (c + 2 < NCH) { STAGE(c + 2, s); CP_COMMIT(); }
    }
#undef STAGE

    // coalesced partial store: P[k][f][b], warp writes 32 consecutive b per f
#pragma unroll
    for (int f = 0; f < 8; f++) {
        float2 v = u2f(acc[f]);
        g_part[((size_t)dsplit * F + ftile + warp * 8 + f) * NB + lane] = v.x + v.y;
    }
}

// ---------------- kernel 3: reduce QKV partials + transpose + fused rope -----------
// grid FQKV/32 = 192 blocks, 256 threads; tile 32 f x 32 b
__global__ void k_reduce_rope(const float* __restrict__ cosv, const float* __restrict__ sinv) {
    __shared__ float t[32][33];
    int f0 = blockIdx.x * 32;
    int tid = threadIdx.x, lane = tid & 31, wp = tid >> 5;
#pragma unroll
    for (int it = 0; it < 4; it++) {
        int fl = it * 8 + wp;
        float s = 0.f;
#pragma unroll
        for (int k = 0; k < NDSPLIT; k++)
            s += g_part[((size_t)k * FQKV + f0 + fl) * NB + lane];
        t[fl][lane] = s;
    }
    __syncthreads();
    bool isq = f0 < 4096;
#pragma unroll
    for (int it = 0; it < 4; it++) {
        int b = it * 8 + wp;
        int fl = lane;
        int f = f0 + fl;
        if (isq) {
            g_qkv[b * FQKV + f] = t[fl][b];
        } else {
            int rel = f - 4096;
            int rr = rel & 1023;
            int j = (rr & 127) >> 1;
            float c = cosv[j], sn = sinv[j];
            int fe = fl & ~1;
            float r = t[fe][b], im = t[fe + 1][b];
            float val = (fl & 1) ? (r * sn + im * c) : (r * c - im * sn);
            float* dst = (rel >= 1024) ? g_vr : g_kr;
            dst[b * (NKV * HD) + rr] = val;
        }
    }
}

// ---------------- kernel 3b: reduce + transpose for WO output ----------------
// grid DIM/32 = 128 blocks
__global__ void k_reduce_out(float* __restrict__ out) {
    __shared__ float t[32][33];
    int f0 = blockIdx.x * 32;
    int tid = threadIdx.x, lane = tid & 31, wp = tid >> 5;
#pragma unroll
    for (int it = 0; it < 4; it++) {
        int fl = it * 8 + wp;
        float s = 0.f;
#pragma unroll
        for (int k = 0; k < NDSPLIT; k++)
            s += g_part[((size_t)k * DIM + f0 + fl) * NB + lane];
        t[fl][lane] = s;
    }
    __syncthreads();
#pragma unroll
    for (int it = 0; it < 4; it++) {
        int b = it * 8 + wp;
        out[b * DIM + f0 + lane] = t[lane][b];
    }
}

// ---------------- kernel 4: flash-decode attention ----------------
// grid (NSPLIT, NKV, NB) = 4096 blocks, 128 threads (4 warps x 32 positions)
#define KROW 36
__global__ void __launch_bounds__(128, 8) k_attn(const float* __restrict__ kc,
                                                 const float* __restrict__ vc) {
    __shared__ __align__(16) float  s_ko[4][32 * KROW];  // K tile, reused as O acc
    __shared__ __align__(16) float4 s_q[4][32];
    __shared__ __align__(16) float4 s_p[128];
    __shared__ float s_wm[4][4], s_wl[4][4], s_mb[4];

    int split = blockIdx.x, kvh = blockIdx.y, b = blockIdx.z;
    int tid = threadIdx.x, lane = tid & 31, warp = tid >> 5;
    int p0 = split * PPS + warp * 32;

    {
        int h = tid >> 5, j4 = tid & 31;
        s_q[h][j4] = ((const float4*)&g_qkv[b * FQKV + (kvh * 4 + h) * HD])[j4];
    }
    __syncthreads();

    // ---- pass 1: scores; each lane owns position p0+lane ----
    float* kbuf = s_ko[warp];
    int r_ = lane >> 3, jj = lane & 7;
    const float* knew = &g_kr[(b * NKV + kvh) * HD];

    float4 pre[8];
#pragma unroll
    for (int i = 0; i < 8; i++) {
        int r = i * 4 + r_;
        int pos = p0 + r;
        const float* src = (pos == POS_NEW) ? knew
                         : kc + (((size_t)b * MAXS + pos) * NKV + kvh) * HD;
        pre[i] = *(const float4*)(src + jj * 4);
    }

    ull acc[4];
#pragma unroll
    for (int h = 0; h < 4; h++) acc[h] = 0ULL;

#pragma unroll
    for (int c = 0; c < 4; c++) {
#pragma unroll
        for (int i = 0; i < 8; i++) {
            int r = i * 4 + r_;
            *(float4*)&kbuf[r * KROW + jj * 4] = pre[i];
        }
        if (c < 3) {
#pragma unroll
            for (int i = 0; i < 8; i++) {
                int r = i * 4 + r_;
                int pos = p0 + r;
                const float* src = (pos == POS_NEW) ? knew
                                 : kc + (((size_t)b * MAXS + pos) * NKV + kvh) * HD;
                pre[i] = *(const float4*)(src + (c + 1) * 32 + jj * 4);
            }
        }
        __syncwarp();
#pragma unroll
        for (int j4 = 0; j4 < 8; j4++) {
            ulonglong2 k2 = *(const ulonglong2*)&kbuf[lane * KROW + j4 * 4];
#pragma unroll
            for (int h = 0; h < 4; h++) {
                ulonglong2 q2 = *(const ulonglong2*)&s_q[h][c * 8 + j4];
                acc[h] = ffma2(q2.x, k2.x, acc[h]);
                acc[h] = ffma2(q2.y, k2.y, acc[h]);
            }
        }
        __syncwarp();
    }

    const float scale = 0.08838834764831845f;  // 1/sqrt(128)
    float sc[4], m[4];
#pragma unroll
    for (int h = 0; h < 4; h++) {
        float2 t = u2f(acc[h]);
        sc[h] = (t.x + t.y) * scale;
        m[h] = sc[h];
    }
#pragma unroll
    for (int off = 16; off > 0; off >>= 1) {
#pragma unroll
        for (int h = 0; h < 4; h++)
            m[h] = fmaxf(m[h], __shfl_xor_sync(0xffffffffu, m[h], off));
    }
    if (lane == 0) {
#pragma unroll
        for (int h = 0; h < 4; h++) s_wm[warp][h] = m[h];
    }
    __syncthreads();

    float mb[4];
#pragma unroll
    for (int h = 0; h < 4; h++) {
        float v = s_wm[0][h];
#pragma unroll
        for (int ww = 1; ww < 4; ww++) v = fmaxf(v, s_wm[ww][h]);
        mb[h] = v;
    }
    float p[4], l[4];
#pragma unroll
    for (int h = 0; h < 4; h++) {
        p[h] = __expf(sc[h] - mb[h]);
        l[h] = p[h];
    }
    s_p[tid] = make_float4(p[0], p[1], p[2], p[3]);
#pragma unroll
    for (int off = 16; off > 0; off >>= 1) {
#pragma unroll
        for (int h = 0; h < 4; h++)
            l[h] += __shfl_xor_sync(0xffffffffu, l[h], off);
    }
    if (lane == 0) {
#pragma unroll
        for (int h = 0; h < 4; h++) s_wl[warp][h] = l[h];
    }
    if (tid < 4) s_mb[tid] = mb[tid];
    __syncthreads();

    // ---- pass 3: O += p * V, rotating 4-deep register prefetch ----
    const float* vnew = &g_vr[(b * NKV + kvh) * HD];
    ull a01[4], a23[4];
#pragma unroll
    for (int h = 0; h < 4; h++) { a01[h] = 0ULL; a23[h] = 0ULL; }

    float4 pv[4];
#pragma unroll
    for (int k = 0; k < 4; k++) {
        int pos = p0 + k;
        const float* vrow = (pos == POS_NEW) ? vnew
                          : vc + (((size_t)b * MAXS + pos) * NKV + kvh) * HD;
        pv[k] = ((const float4*)vrow)[lane];
    }
#pragma unroll
    for (int g = 0; g < 8; g++) {
#pragma unroll
        for (int k = 0; k < 4; k++) {
            float4 cur = pv[k];
            if (g < 7) {
                int pos = p0 + (g + 1) * 4 + k;
                const float* vrow = (pos == POS_NEW) ? vnew
                                  : vc + (((size_t)b * MAXS + pos) * NKV + kvh) * HD;
                pv[k] = ((const float4*)vrow)[lane];
            }
            ulonglong2 vv = *(const ulonglong2*)&cur;
            float4 pp = s_p[warp * 32 + g * 4 + k];
            ull pu;
            pu = f2u(pp.x, pp.x); a01[0] = ffma2(pu, vv.x, a01[0]); a23[0] = ffma2(pu, vv.y, a23[0]);
            pu = f2u(pp.y, pp.y); a01[1] = ffma2(pu, vv.x, a01[1]); a23[1] = ffma2(pu, vv.y, a23[1]);
            pu = f2u(pp.z, pp.z); a01[2] = ffma2(pu, vv.x, a01[2]); a23[2] = ffma2(pu, vv.y, a23[2]);
            pu = f2u(pp.w, pp.w); a01[3] = ffma2(pu, vv.x, a01[3]); a23[3] = ffma2(pu, vv.y, a23[3]);
        }
    }
    float* os = &s_ko[0][0];
#pragma unroll
    for (int h = 0; h < 4; h++) {
        float2 lo = u2f(a01[h]), hi = u2f(a23[h]);
        *(float4*)&os[(warp * 4 + h) * HD + lane * 4] = make_float4(lo.x, lo.y, hi.x, hi.y);
    }
    __syncthreads();

    // ---- final: cross-warp sum (4 warps), write partials ----
#pragma unroll
    for (int k = 0; k < 4; k++) {
        int o = tid + k * 128;
        int h = o >> 7, d = o & 127;
        float s = 0.f;
#pragma unroll
        for (int ww = 0; ww < 4; ww++) s += os[(ww * 4 + h) * HD + d];
        g_po[(((size_t)split * NB + b) * NH + kvh * 4 + h) * HD + d] = s;
    }
    if (tid < 4) {
        float gl = 0.f;
#pragma unroll
        for (int ww = 0; ww < 4; ww++) gl += s_wl[ww][tid];
        g_pl[((size_t)split * NB + b) * NH + kvh * 4 + tid] = gl;
        g_pm[((size_t)split * NB + b) * NH + kvh * 4 + tid] = s_mb[tid];
    }
}

// ---------------- kernel 6: combine splits, write attn transposed ----------------
__global__ void k_combine() {
    int gh = blockIdx.x, b = blockIdx.y;
    int t = threadIdx.x;
    __shared__ float s_w[NSPLIT];
    __shared__ float s_gl;
    if (t == 0) {
        float ms[NSPLIT];
        float gm = -1e30f;
#pragma unroll
        for (int s = 0; s < NSPLIT; s++) {
            ms[s] = g_pm[((size_t)s * NB + b) * NH + gh];
            gm = fmaxf(gm, ms[s]);
        }
        float gl = 0.f;
#pragma unroll
        for (int s = 0; s < NSPLIT; s++) {
            float wv = __expf(ms[s] - gm);
            s_w[s] = wv;
            gl += wv * g_pl[((size_t)s * NB + b) * NH + gh];
        }
        s_gl = gl;
    }
    __syncthreads();
    float inv = 1.0f / s_gl;
    float o0 = 0.f, o1 = 0.f;
#pragma unroll
    for (int s = 0; s < NSPLIT; s++) {
        const float* po = &g_po[(((size_t)s * NB + b) * NH + gh) * HD];
        float wv = s_w[s];
        o0 += wv * po[2 * t];
        o1 += wv * po[2 * t + 1];
    }
    g_at2[(size_t)(gh * 64 + t) * NB + b] = make_float2(o0 * inv, o1 * inv);
}

// ---------------- launcher ----------------
extern "C" void kernel_launch(void* const* d_in, const int* in_sizes, int n_in,
                              void* d_out, int out_size) {
    const float* x  = (const float*)d_in[0];
    const float* tc = (const float*)d_in[2];
    const float* ts = (const float*)d_in[3];
    const float* wq = (const float*)d_in[4];
    const float* wk = (const float*)d_in[5];
    const float* wv = (const float*)d_in[6];
    const float* wo = (const float*)d_in[7];
    const float* kc = (const float*)d_in[8];
    const float* vc = (const float*)d_in[9];
    float* out = (float*)d_out;

    k_transpose<<<64, 256>>>(x);
    k_gemm<<<dim3(FQKV / 64, NDSPLIT), 256>>>(0, wq, wk, wv, FQKV);
    k_reduce_rope<<<FQKV / 32, 256>>>(tc, ts);
    k_attn<<<dim3(NSPLIT, NKV, NB), 128>>>(kc, vc);
    k_combine<<<dim3(NH, NB), 64>>>();
    k_gemm<<<dim3(DIM / 64, NDSPLIT), 256>>>(1, wo, nullptr, nullptr, DIM);
    k_reduce_out<<<DIM / 32, 256>>>(out);
}

// round 7
// speedup vs baseline: 1.6399x; 1.1400x over previous
#include <cuda_runtime.h>

#define NB 32
#define DIM 4096
#define NH 32
#define NKV 8
#define HD 128
#define MAXS 4096
#define POS_NEW 2047
#define NSPLIT 16
#define PPS 128          // attn positions per split (2048/16)
#define FQKV 6144
#define NS_QKV 9
#define NS_WO 13
#define CHD 32           // d per gemm chunk
#define NCHT (DIM / CHD) // 128 total chunks

typedef unsigned long long ull;

__device__ __forceinline__ ull ffma2(ull a, ull b, ull c) {
    ull d;
    asm("fma.rn.f32x2 %0, %1, %2, %3;" : "=l"(d) : "l"(a), "l"(b), "l"(c));
    return d;
}
__device__ __forceinline__ float2 u2f(ull r) {
    float2 v;
    asm("mov.b64 {%0, %1}, %2;" : "=f"(v.x), "=f"(v.y) : "l"(r));
    return v;
}
__device__ __forceinline__ ull f2u(float x, float y) {
    ull r;
    asm("mov.b64 %0, {%1, %2};" : "=l"(r) : "f"(x), "f"(y));
    return r;
}
__device__ __forceinline__ unsigned smem_u32(const void* p) {
    return (unsigned)__cvta_generic_to_shared(p);
}
#define CP16(dst, src) \
    asm volatile("cp.async.cg.shared.global [%0], [%1], 16;" :: "r"(dst), "l"(src))
#define CP_COMMIT() asm volatile("cp.async.commit_group;")
#define CP_WAIT1()  asm volatile("cp.async.wait_group 1;")
#define CP_WAIT0()  asm volatile("cp.async.wait_group 0;")

// ---------------- scratch ----------------
__device__ __align__(16) float g_part[16 * FQKV * NB];     // P[k][f][b]
__device__ __align__(16) float g_qkv[NB * FQKV];
__device__ __align__(16) float g_kr[NB * NKV * HD];
__device__ __align__(16) float g_vr[NB * NKV * HD];
__device__ __align__(16) float g_attn[NB * DIM];           // attn out, natural layout
__device__ __align__(16) float g_po[NSPLIT * NB * NH * HD];
__device__ float g_pm[NSPLIT * NB * NH];
__device__ float g_pl[NSPLIT * NB * NH];

// ---------------- kernel 1: skinny GEMM, 4f x 4b register tiles, d-pair FFMA2 -------
// out[b][f] = sum_d x[b][d] * w[f][d]; partials P[k][f][b].
// block 256: fg = tid>>3 (0..31), bg = tid&7 (0..7); f = ftile+fg+32j, b = bg+8i.
__global__ void __launch_bounds__(256, 3)
k_gemm(int mode, int ns, const float* __restrict__ xg,
       const float* __restrict__ w0, const float* __restrict__ w1,
       const float* __restrict__ w2, int F) {
    __shared__ __align__(16) float ws[2][128][CHD + 4];  // 36.0 KB
    __shared__ __align__(16) float xs[2][32][CHD + 4];   //  9.0 KB
    int tid = threadIdx.x;
    int fg = tid >> 3, bg = tid & 7;
    int ftile = blockIdx.x * 128;
    int dsplit = blockIdx.y;
    int c0 = dsplit * NCHT / ns;
    int c1 = (dsplit + 1) * NCHT / ns;

    const float* w = w0;
    int frow = ftile;
    if (mode == 0) {
        if (ftile >= 5120)      { w = w2; frow = ftile - 5120; }
        else if (ftile >= 4096) { w = w1; frow = ftile - 4096; }
    }
    const float* wb = w + (size_t)frow * DIM;

#define STAGE(c, s) do {                                                  \
        int d0_ = (c) * CHD;                                              \
        _Pragma("unroll")                                                 \
        for (int i_ = 0; i_ < 4; i_++) {                                  \
            int item = i_ * 256 + tid;                                    \
            int r = item >> 3, cc = item & 7;                             \
            CP16(smem_u32(&ws[s][r][cc * 4]),                             \
                 wb + (size_t)r * DIM + d0_ + cc * 4);                    \
        }                                                                 \
        {                                                                 \
            int r = tid >> 3, cc = tid & 7;                               \
            CP16(smem_u32(&xs[s][r][cc * 4]),                             \
                 xg + (size_t)r * DIM + d0_ + cc * 4);                    \
        }                                                                 \
    } while (0)

    STAGE(c0, 0); CP_COMMIT();
    STAGE(c0 + 1, 1); CP_COMMIT();

    ull acc[4][4];
#pragma unroll
    for (int j = 0; j < 4; j++)
#pragma unroll
        for (int i = 0; i < 4; i++) acc[j][i] = 0ULL;

    for (int c = c0; c < c1; c++) {
        int s = (c - c0) & 1;
        if (c < c1 - 1) CP_WAIT1(); else CP_WAIT0();
        __syncthreads();
#pragma unroll
        for (int d4 = 0; d4 < CHD; d4 += 4) {
            ulonglong2 xv[4], wv[4];
#pragma unroll
            for (int i = 0; i < 4; i++)
                xv[i] = *(const ulonglong2*)&xs[s][bg + 8 * i][d4];
#pragma unroll
            for (int j = 0; j < 4; j++)
                wv[j] = *(const ulonglong2*)&ws[s][fg + 32 * j][d4];
#pragma unroll
            for (int j = 0; j < 4; j++)
#pragma unroll
                for (int i = 0; i < 4; i++) {
                    acc[j][i] = ffma2(wv[j].x, xv[i].x, acc[j][i]);
                    acc[j][i] = ffma2(wv[j].y, xv[i].y, acc[j][i]);
                }
        }
        __syncthreads();
        if (c + 2 < c1) { STAGE(c + 2, s); CP_COMMIT(); }
    }
#undef STAGE

#pragma unroll
    for (int j = 0; j < 4; j++)
#pragma unroll
        for (int i = 0; i < 4; i++) {
            float2 v = u2f(acc[j][i]);
            g_part[((size_t)dsplit * F + ftile + fg + 32 * j) * NB + bg + 8 * i] = v.x + v.y;
        }
}

// ---------------- kernel 2: reduce QKV partials + transpose + fused rope -----------
// grid FQKV/32 = 192 blocks, 256 threads; tile 32 f x 32 b
__global__ void k_reduce_rope(const float* __restrict__ cosv, const float* __restrict__ sinv) {
    __shared__ float t[32][33];
    int f0 = blockIdx.x * 32;
    int tid = threadIdx.x, lane = tid & 31, wp = tid >> 5;
#pragma unroll
    for (int it = 0; it < 4; it++) {
        int fl = it * 8 + wp;
        float s = 0.f;
        for (int k = 0; k < NS_QKV; k++)
            s += g_part[((size_t)k * FQKV + f0 + fl) * NB + lane];
        t[fl][lane] = s;
    }
    __syncthreads();
    bool isq = f0 < 4096;
#pragma unroll
    for (int it = 0; it < 4; it++) {
        int b = it * 8 + wp;
        int fl = lane;
        int f = f0 + fl;
        if (isq) {
            g_qkv[b * FQKV + f] = t[fl][b];
        } else {
            int rel = f - 4096;
            int rr = rel & 1023;
            int j = (rr & 127) >> 1;
            float c = cosv[j], sn = sinv[j];
            int fe = fl & ~1;
            float r = t[fe][b], im = t[fe + 1][b];
            float val = (fl & 1) ? (r * sn + im * c) : (r * c - im * sn);
            float* dst = (rel >= 1024) ? g_vr : g_kr;
            dst[b * (NKV * HD) + rr] = val;
        }
    }
}

// ---------------- kernel 2b: reduce + transpose for WO output ----------------
__global__ void k_reduce_out(float* __restrict__ out) {
    __shared__ float t[32][33];
    int f0 = blockIdx.x * 32;
    int tid = threadIdx.x, lane = tid & 31, wp = tid >> 5;
#pragma unroll
    for (int it = 0; it < 4; it++) {
        int fl = it * 8 + wp;
        float s = 0.f;
        for (int k = 0; k < NS_WO; k++)
            s += g_part[((size_t)k * DIM + f0 + fl) * NB + lane];
        t[fl][lane] = s;
    }
    __syncthreads();
#pragma unroll
    for (int it = 0; it < 4; it++) {
        int b = it * 8 + wp;
        out[b * DIM + f0 + lane] = t[lane][b];
    }
}

// ---------------- kernel 3: flash-decode attention ----------------
// grid (NSPLIT, NKV, NB) = 4096 blocks, 128 threads (4 warps x 32 positions)
#define KROW 36
__global__ void __launch_bounds__(128, 8) k_attn(const float* __restrict__ kc,
                                                 const float* __restrict__ vc) {
    __shared__ __align__(16) float  s_ko[4][32 * KROW];  // K tile, reused as O acc
    __shared__ __align__(16) float4 s_q[4][32];
    __shared__ __align__(16) float4 s_p[128];
    __shared__ float s_wm[4][4], s_wl[4][4], s_mb[4];

    int split = blockIdx.x, kvh = blockIdx.y, b = blockIdx.z;
    int tid = threadIdx.x, lane = tid & 31, warp = tid >> 5;
    int p0 = split * PPS + warp * 32;

    {
        int h = tid >> 5, j4 = tid & 31;
        s_q[h][j4] = ((const float4*)&g_qkv[b * FQKV + (kvh * 4 + h) * HD])[j4];
    }
    __syncthreads();

    // ---- pass 1: scores; each lane owns position p0+lane ----
    float* kbuf = s_ko[warp];
    int r_ = lane >> 3, jj = lane & 7;
    const float* knew = &g_kr[(b * NKV + kvh) * HD];

    float4 pre[8];
#pragma unroll
    for (int i = 0; i < 8; i++) {
        int r = i * 4 + r_;
        int pos = p0 + r;
        const float* src = (pos == POS_NEW) ? knew
                         : kc + (((size_t)b * MAXS + pos) * NKV + kvh) * HD;
        pre[i] = *(const float4*)(src + jj * 4);
    }

    ull acc[4];
#pragma unroll
    for (int h = 0; h < 4; h++) acc[h] = 0ULL;

#pragma unroll
    for (int c = 0; c < 4; c++) {
#pragma unroll
        for (int i = 0; i < 8; i++) {
            int r = i * 4 + r_;
            *(float4*)&kbuf[r * KROW + jj * 4] = pre[i];
        }
        if (c < 3) {
#pragma unroll
            for (int i = 0; i < 8; i++) {
                int r = i * 4 + r_;
                int pos = p0 + r;
                const float* src = (pos == POS_NEW) ? knew
                                 : kc + (((size_t)b * MAXS + pos) * NKV + kvh) * HD;
                pre[i] = *(const float4*)(src + (c + 1) * 32 + jj * 4);
            }
        }
        __syncwarp();
#pragma unroll
        for (int j4 = 0; j4 < 8; j4++) {
            ulonglong2 k2 = *(const ulonglong2*)&kbuf[lane * KROW + j4 * 4];
#pragma unroll
            for (int h = 0; h < 4; h++) {
                ulonglong2 q2 = *(const ulonglong2*)&s_q[h][c * 8 + j4];
                acc[h] = ffma2(q2.x, k2.x, acc[h]);
                acc[h] = ffma2(q2.y, k2.y, acc[h]);
            }
        }
        __syncwarp();
    }

    const float scale = 0.08838834764831845f;  // 1/sqrt(128)
    float sc[4], m[4];
#pragma unroll
    for (int h = 0; h < 4; h++) {
        float2 t = u2f(acc[h]);
        sc[h] = (t.x + t.y) * scale;
        m[h] = sc[h];
    }
#pragma unroll
    for (int off = 16; off > 0; off >>= 1) {
#pragma unroll
        for (int h = 0; h < 4; h++)
            m[h] = fmaxf(m[h], __shfl_xor_sync(0xffffffffu, m[h], off));
    }
    if (lane == 0) {
#pragma unroll
        for (int h = 0; h < 4; h++) s_wm[warp][h] = m[h];
    }
    __syncthreads();

    float mb[4];
#pragma unroll
    for (int h = 0; h < 4; h++) {
        float v = s_wm[0][h];
#pragma unroll
        for (int ww = 1; ww < 4; ww++) v = fmaxf(v, s_wm[ww][h]);
        mb[h] = v;
    }
    float p[4], l[4];
#pragma unroll
    for (int h = 0; h < 4; h++) {
        p[h] = __expf(sc[h] - mb[h]);
        l[h] = p[h];
    }
    s_p[tid] = make_float4(p[0], p[1], p[2], p[3]);
#pragma unroll
    for (int off = 16; off > 0; off >>= 1) {
#pragma unroll
        for (int h = 0; h < 4; h++)
            l[h] += __shfl_xor_sync(0xffffffffu, l[h], off);
    }
    if (lane == 0) {
#pragma unroll
        for (int h = 0; h < 4; h++) s_wl[warp][h] = l[h];
    }
    if (tid < 4) s_mb[tid] = mb[tid];
    __syncthreads();

    // ---- pass 3: O += p * V, rotating 4-deep register prefetch ----
    const float* vnew = &g_vr[(b * NKV + kvh) * HD];
    ull a01[4], a23[4];
#pragma unroll
    for (int h = 0; h < 4; h++) { a01[h] = 0ULL; a23[h] = 0ULL; }

    float4 pv[4];
#pragma unroll
    for (int k = 0; k < 4; k++) {
        int pos = p0 + k;
        const float* vrow = (pos == POS_NEW) ? vnew
                          : vc + (((size_t)b * MAXS + pos) * NKV + kvh) * HD;
        pv[k] = ((const float4*)vrow)[lane];
    }
#pragma unroll
    for (int g = 0; g < 8; g++) {
#pragma unroll
        for (int k = 0; k < 4; k++) {
            float4 cur = pv[k];
            if (g < 7) {
                int pos = p0 + (g + 1) * 4 + k;
                const float* vrow = (pos == POS_NEW) ? vnew
                                  : vc + (((size_t)b * MAXS + pos) * NKV + kvh) * HD;
                pv[k] = ((const float4*)vrow)[lane];
            }
            ulonglong2 vv = *(const ulonglong2*)&cur;
            float4 pp = s_p[warp * 32 + g * 4 + k];
            ull pu;
            pu = f2u(pp.x, pp.x); a01[0] = ffma2(pu, vv.x, a01[0]); a23[0] = ffma2(pu, vv.y, a23[0]);
            pu = f2u(pp.y, pp.y); a01[1] = ffma2(pu, vv.x, a01[1]); a23[1] = ffma2(pu, vv.y, a23[1]);
            pu = f2u(pp.z, pp.z); a01[2] = ffma2(pu, vv.x, a01[2]); a23[2] = ffma2(pu, vv.y, a23[2]);
            pu = f2u(pp.w, pp.w); a01[3] = ffma2(pu, vv.x, a01[3]); a23[3] = ffma2(pu, vv.y, a23[3]);
        }
    }
    float* os = &s_ko[0][0];
#pragma unroll
    for (int h = 0; h < 4; h++) {
        float2 lo = u2f(a01[h]), hi = u2f(a23[h]);
        *(float4*)&os[(warp * 4 + h) * HD + lane * 4] = make_float4(lo.x, lo.y, hi.x, hi.y);
    }
    __syncthreads();

#pragma unroll
    for (int k = 0; k < 4; k++) {
        int o = tid + k * 128;
        int h = o >> 7, d = o & 127;
        float s = 0.f;
#pragma unroll
        for (int ww = 0; ww < 4; ww++) s += os[(ww * 4 + h) * HD + d];
        g_po[(((size_t)split * NB + b) * NH + kvh * 4 + h) * HD + d] = s;
    }
    if (tid < 4) {
        float gl = 0.f;
#pragma unroll
        for (int ww = 0; ww < 4; ww++) gl += s_wl[ww][tid];
        g_pl[((size_t)split * NB + b) * NH + kvh * 4 + tid] = gl;
        g_pm[((size_t)split * NB + b) * NH + kvh * 4 + tid] = s_mb[tid];
    }
}

// ---------------- kernel 4: combine splits, natural [b][dim] output ----------------
__global__ void k_combine() {
    int gh = blockIdx.x, b = blockIdx.y;
    int t = threadIdx.x;
    __shared__ float s_w[NSPLIT];
    __shared__ float s_gl;
    if (t == 0) {
        float ms[NSPLIT];
        float gm = -1e30f;
#pragma unroll
        for (int s = 0; s < NSPLIT; s++) {
            ms[s] = g_pm[((size_t)s * NB + b) * NH + gh];
            gm = fmaxf(gm, ms[s]);
        }
        float gl = 0.f;
#pragma unroll
        for (int s = 0; s < NSPLIT; s++) {
            float wv = __expf(ms[s] - gm);
            s_w[s] = wv;
            gl += wv * g_pl[((size_t)s * NB + b) * NH + gh];
        }
        s_gl = gl;
    }
    __syncthreads();
    float inv = 1.0f / s_gl;
    float o0 = 0.f, o1 = 0.f;
#pragma unroll
    for (int s = 0; s < NSPLIT; s++) {
        const float* po = &g_po[(((size_t)s * NB + b) * NH + gh) * HD];
        float wv = s_w[s];
        o0 += wv * po[2 * t];
        o1 += wv * po[2 * t + 1];
    }
    g_attn[b * DIM + gh * HD + 2 * t]     = o0 * inv;
    g_attn[b * DIM + gh * HD + 2 * t + 1] = o1 * inv;
}

// ---------------- launcher ----------------
extern "C" void kernel_launch(void* const* d_in, const int* in_sizes, int n_in,
                              void* d_out, int out_size) {
    const float* x  = (const float*)d_in[0];
    const float* tc = (const float*)d_in[2];
    const float* ts = (const float*)d_in[3];
    const float* wq = (const float*)d_in[4];
    const float* wk = (const float*)d_in[5];
    const float* wv = (const float*)d_in[6];
    const float* wo = (const float*)d_in[7];
    const float* kc = (const float*)d_in[8];
    const float* vc = (const float*)d_in[9];
    float* out = (float*)d_out;

    float* g_attn_p = nullptr;
    cudaGetSymbolAddress((void**)&g_attn_p, g_attn);

    k_gemm<<<dim3(FQKV / 128, NS_QKV), 256>>>(0, NS_QKV, x, wq, wk, wv, FQKV);
    k_reduce_rope<<<FQKV / 32, 256>>>(tc, ts);
    k_attn<<<dim3(NSPLIT, NKV, NB), 128>>>(kc, vc);
    k_combine<<<dim3(NH, NB), 64>>>();
    k_gemm<<<dim3(DIM / 128, NS_WO), 256>>>(1, NS_WO, g_attn_p, wo, nullptr, nullptr, DIM);
    k_reduce_out<<<DIM / 32, 256>>>(out);
}